// round 11
// baseline (speedup 1.0000x reference)
#include <cuda_runtime.h>
#include <cuda_bf16.h>
#include <cstdint>

#define NNODES 50000
#define NEDGES 800000
#define MPAD   50048      // 391 * 128
#define C1 256            // heads*hid layer1
#define C2 128            // out channels layer2
#define NEG_SLOPE 0.2f
#define EPS_DEN 1e-16f

// ---------------- scratch (device globals; no allocations allowed) ----------------
__device__ float g_xl1[NNODES * C1];
__device__ float g_xr1[NNODES * C1];
__device__ float g_hl2[NNODES * C2];
__device__ float g_hr2[NNODES * C2];
__device__ int   g_row[NNODES + 1];
__device__ int   g_cnt[NNODES];
__device__ int   g_srcs[NEDGES];
// bf16 split buffers
__device__ __align__(16) __nv_bfloat16 g_ah[MPAD * 256];
__device__ __align__(16) __nv_bfloat16 g_al[MPAD * 256];
__device__ __align__(16) __nv_bfloat16 g_bhL[32768];
__device__ __align__(16) __nv_bfloat16 g_blL[32768];
__device__ __align__(16) __nv_bfloat16 g_bhR[32768];
__device__ __align__(16) __nv_bfloat16 g_blR[32768];
__device__ __align__(16) __nv_bfloat16 g_bhL2[32768];
__device__ __align__(16) __nv_bfloat16 g_blL2[32768];
__device__ __align__(16) __nv_bfloat16 g_bhR2[32768];
__device__ __align__(16) __nv_bfloat16 g_blR2[32768];

// ---------------- helpers ----------------
__device__ __forceinline__ float lrelu(float x) { return x > 0.f ? x : NEG_SLOPE * x; }

__device__ __forceinline__ uint32_t smem_u32(const void* p) {
    uint32_t a;
    asm("{ .reg .u64 t; cvta.to.shared.u64 t, %1; cvt.u32.u64 %0, t; }" : "=r"(a) : "l"(p));
    return a;
}

__device__ __forceinline__ void ldsm_x4(uint32_t* r, uint32_t addr) {
    asm volatile("ldmatrix.sync.aligned.m8n8.x4.shared.b16 {%0,%1,%2,%3}, [%4];"
                 : "=r"(r[0]), "=r"(r[1]), "=r"(r[2]), "=r"(r[3]) : "r"(addr));
}

__device__ __forceinline__ void mma_bf16(float* c, const uint32_t* a,
                                         uint32_t b0, uint32_t b1) {
    asm volatile(
        "mma.sync.aligned.m16n8k16.row.col.f32.bf16.bf16.f32 "
        "{%0,%1,%2,%3}, {%4,%5,%6,%7}, {%8,%9}, {%0,%1,%2,%3};"
        : "+f"(c[0]), "+f"(c[1]), "+f"(c[2]), "+f"(c[3])
        : "r"(a[0]), "r"(a[1]), "r"(a[2]), "r"(a[3]), "r"(b0), "r"(b1));
}

#define CP_ASYNC16(dst, src) \
    asm volatile("cp.async.cg.shared.global [%0], [%1], 16;" :: "r"(dst), "l"(src))
#define CP_COMMIT() asm volatile("cp.async.commit_group;")
#define CP_WAIT1()  asm volatile("cp.async.wait_group 1;")
#define CP_WAIT0()  asm volatile("cp.async.wait_group 0;")

// ---------------- CSR build ----------------
__global__ void k_zero() {
    int i = blockIdx.x * blockDim.x + threadIdx.x;
    if (i < NNODES) g_cnt[i] = 0;
}
__global__ void k_count(const int* __restrict__ ei) {
    int e = blockIdx.x * blockDim.x + threadIdx.x;
    if (e < NEDGES) atomicAdd(&g_cnt[ei[NEDGES + e]], 1);
}
__global__ __launch_bounds__(1024) void k_scan() {
    __shared__ int s[1024];
    __shared__ int carry_s;
    int t = threadIdx.x;
    if (t == 0) carry_s = 0;
    __syncthreads();
    for (int base = 0; base < NNODES; base += 4096) {
        int idx = base + t * 4;
        int v0 = (idx + 0 < NNODES) ? g_cnt[idx + 0] : 0;
        int v1 = (idx + 1 < NNODES) ? g_cnt[idx + 1] : 0;
        int v2 = (idx + 2 < NNODES) ? g_cnt[idx + 2] : 0;
        int v3 = (idx + 3 < NNODES) ? g_cnt[idx + 3] : 0;
        int tot = v0 + v1 + v2 + v3;
        s[t] = tot;
        __syncthreads();
        for (int off = 1; off < 1024; off <<= 1) {
            int x = (t >= off) ? s[t - off] : 0;
            __syncthreads();
            s[t] += x;
            __syncthreads();
        }
        int excl = carry_s + s[t] - tot;
        if (idx + 0 < NNODES) { g_row[idx + 0] = excl;                g_cnt[idx + 0] = 0; }
        if (idx + 1 < NNODES) { g_row[idx + 1] = excl + v0;           g_cnt[idx + 1] = 0; }
        if (idx + 2 < NNODES) { g_row[idx + 2] = excl + v0 + v1;      g_cnt[idx + 2] = 0; }
        if (idx + 3 < NNODES) { g_row[idx + 3] = excl + v0 + v1 + v2; g_cnt[idx + 3] = 0; }
        __syncthreads();
        if (t == 1023) carry_s += s[1023];
        __syncthreads();
    }
    if (t == 0) g_row[NNODES] = NEDGES;
}
__global__ void k_fill(const int* __restrict__ ei) {
    int e = blockIdx.x * blockDim.x + threadIdx.x;
    if (e >= NEDGES) return;
    int dst = ei[NEDGES + e];
    int pos = g_row[dst] + atomicAdd(&g_cnt[dst], 1);
    g_srcs[pos] = ei[e];
}

// ---------------- bf16 hi/lo splits ----------------
__global__ void k_split(const float* __restrict__ A, int M, int K) {
    int i = blockIdx.x * blockDim.x + threadIdx.x;
    if (i >= MPAD * K) return;
    int m = i / K;
    float v = (m < M) ? A[i] : 0.f;
    __nv_bfloat16 h = __float2bfloat16(v);
    g_ah[i] = h;
    g_al[i] = __float2bfloat16(v - __bfloat162float(h));
}
// W [K x Nn] fp32 -> bh/bl [Nn x K] bf16 (transposed)
__global__ void k_splitw(const float* __restrict__ W, __nv_bfloat16* __restrict__ bh,
                         __nv_bfloat16* __restrict__ bl, int K, int Nn) {
    int i = blockIdx.x * blockDim.x + threadIdx.x;
    if (i >= K * Nn) return;
    int k = i / Nn, n = i - k * Nn;
    float v = W[i];
    __nv_bfloat16 h = __float2bfloat16(v);
    bh[n * K + k] = h;
    bl[n * K + k] = __float2bfloat16(v - __bfloat162float(h));
}

// ---------------- warp-MMA bf16x3 GEMM, cp.async double-buffered ------------------
// KS = row stride of A/B (elems); KT = K width. Full-K serial schedule.
template <int KS, int KT, int NPER>
__global__ __launch_bounds__(256) void mgemm(
    const __nv_bfloat16* __restrict__ Ah, const __nv_bfloat16* __restrict__ Al,
    const __nv_bfloat16* __restrict__ Bh0, const __nv_bfloat16* __restrict__ Bl0,
    const __nv_bfloat16* __restrict__ Bh1, const __nv_bfloat16* __restrict__ Bl1,
    float* __restrict__ Cd0, float* __restrict__ Cd1) {
    constexpr int KCH = KT / 64;
    constexpr int NCH = 3 * KCH;
    constexpr int NB  = NPER / 128;
    extern __shared__ char dsm[];

    const int tid = threadIdx.x, wid = tid >> 5, lane = tid & 31;
    const int mat  = blockIdx.y / NB;
    const int ncol = (blockIdx.y % NB) * 128;
    const __nv_bfloat16* Bh = mat ? Bh1 : Bh0;
    const __nv_bfloat16* Bl = mat ? Bl1 : Bl0;
    float* Cd = mat ? Cd1 : Cd0;
    const size_t blockM = (size_t)blockIdx.x * 128;

    const int wm = wid >> 1, wn = wid & 1;
    float acc[2][8][4];
#pragma unroll
    for (int mi = 0; mi < 2; mi++)
#pragma unroll
        for (int ni = 0; ni < 8; ni++)
#pragma unroll
            for (int q = 0; q < 4; q++) acc[mi][ni][q] = 0.f;

    const int a_r = (lane & 7) + ((lane >> 3) & 1) * 8;
    const int a_c = (lane >> 4) * 8;
    const int b_r = (lane & 7) + (lane >> 4) * 8;
    const int b_c = ((lane >> 3) & 1) * 8;

    auto issue = [&](int c, int s) {
        int seg = c / KCH;
        int kc = (c - seg * KCH) * 64;
        const __nv_bfloat16* Asrc = (seg == 2) ? Al : Ah;
        const __nv_bfloat16* Bsrc = (seg == 1) ? Bl : Bh;
        char* abase = dsm + s * 36864;
        char* bbase = abase + 18432;
#pragma unroll
        for (int u = tid; u < 1024; u += 256) {
            int r = u >> 3, j = u & 7;
            CP_ASYNC16(smem_u32(abase + r * 144 + j * 16),
                       Asrc + (blockM + r) * KS + kc + j * 8);
            CP_ASYNC16(smem_u32(bbase + r * 144 + j * 16),
                       Bsrc + (size_t)(ncol + r) * KS + kc + j * 8);
        }
        CP_COMMIT();
    };

    issue(0, 0);
    for (int c = 0; c < NCH; c++) {
        if (c + 1 < NCH) { issue(c + 1, (c + 1) & 1); CP_WAIT1(); }
        else             { CP_WAIT0(); }
        __syncthreads();
        char* abase = dsm + (c & 1) * 36864;
        char* bbase = abase + 18432;
#pragma unroll
        for (int ks = 0; ks < 4; ks++) {
            int k0 = ks * 16;
            uint32_t a[2][4];
#pragma unroll
            for (int mi = 0; mi < 2; mi++)
                ldsm_x4(a[mi], smem_u32(abase + (wm * 32 + mi * 16 + a_r) * 144 +
                                        (k0 + a_c) * 2));
            uint32_t b[4][4];
#pragma unroll
            for (int np = 0; np < 4; np++)
                ldsm_x4(b[np], smem_u32(bbase + (wn * 64 + np * 16 + b_r) * 144 +
                                        (k0 + b_c) * 2));
#pragma unroll
            for (int mi = 0; mi < 2; mi++)
#pragma unroll
                for (int ni = 0; ni < 8; ni++)
                    mma_bf16(acc[mi][ni], a[mi],
                             b[ni >> 1][(ni & 1) * 2], b[ni >> 1][(ni & 1) * 2 + 1]);
        }
        __syncthreads();
    }

#pragma unroll
    for (int mi = 0; mi < 2; mi++) {
        int r0 = (int)blockM + wm * 32 + mi * 16 + (lane >> 2);
#pragma unroll
        for (int ni = 0; ni < 8; ni++) {
            int col = ncol + wn * 64 + ni * 8 + (lane & 3) * 2;
            if (r0 < NNODES)
                *(float2*)&Cd[(size_t)r0 * NPER + col] =
                    make_float2(acc[mi][ni][0], acc[mi][ni][1]);
            if (r0 + 8 < NNODES)
                *(float2*)&Cd[(size_t)(r0 + 8) * NPER + col] =
                    make_float2(acc[mi][ni][2], acc[mi][ni][3]);
        }
    }
}

// ---------------- layer 1 aggregation: half heads, 4 edges/warp-iter --------------
// warp per node; lane = g*8 + gl (4 groups of 8 lanes); group g = edge jb+g.
// gl covers 16 channels; head = 4-lane subset (gl<4 -> head A, gl>=4 -> head B),
// so the logit reduce is xor 1,2 only. Group combine at end via xor 8,16.
__global__ __launch_bounds__(256) void aggr1h(const float* __restrict__ att,
                                              const float* __restrict__ b1,
                                              int half) {
    int node = blockIdx.x * 8 + (threadIdx.x >> 5);
    if (node >= NNODES) return;
    int lane = threadIdx.x & 31;
    int g  = lane >> 3;
    int gl = lane & 7;
    int beg = g_row[node], end = g_row[node + 1];
    int ch = half * 128 + gl * 16;

    const float4* pr = (const float4*)(g_xr1 + (size_t)node * C1 + ch);
    float4 r0 = pr[0], r1 = pr[1], r2 = pr[2], r3 = pr[3];
    const float4* pa = (const float4*)(att + ch);
    float4 t0 = pa[0], t1 = pa[1], t2 = pa[2], t3 = pa[3];

    float acc[16];
#pragma unroll
    for (int q = 0; q < 16; q++) acc[q] = 0.f;
    float den = 0.f;

    int i = beg;
    while (i < end) {
        int cnt = min(32, end - i);
        int mysrc = __ldg(&g_srcs[i + min(lane, cnt - 1)]);
        for (int jb = 0; jb < cnt; jb += 4) {
            int idx = min(jb + g, cnt - 1);
            int src = __shfl_sync(0xffffffffu, mysrc, idx);
            bool valid = (jb + g) < cnt;
            const float4* pl = (const float4*)(g_xl1 + (size_t)src * C1 + ch);
            float4 a0 = __ldg(pl), a1 = __ldg(pl + 1), a2 = __ldg(pl + 2), a3 = __ldg(pl + 3);
            float s = lrelu(a0.x + r0.x) * t0.x + lrelu(a0.y + r0.y) * t0.y +
                      lrelu(a0.z + r0.z) * t0.z + lrelu(a0.w + r0.w) * t0.w +
                      lrelu(a1.x + r1.x) * t1.x + lrelu(a1.y + r1.y) * t1.y +
                      lrelu(a1.z + r1.z) * t1.z + lrelu(a1.w + r1.w) * t1.w +
                      lrelu(a2.x + r2.x) * t2.x + lrelu(a2.y + r2.y) * t2.y +
                      lrelu(a2.z + r2.z) * t2.z + lrelu(a2.w + r2.w) * t2.w +
                      lrelu(a3.x + r3.x) * t3.x + lrelu(a3.y + r3.y) * t3.y +
                      lrelu(a3.z + r3.z) * t3.z + lrelu(a3.w + r3.w) * t3.w;
            s += __shfl_xor_sync(0xffffffffu, s, 1);
            s += __shfl_xor_sync(0xffffffffu, s, 2);   // per-head sum (4 lanes x 16 ch)
            float ee = valid ? __expf(s) : 0.f;
            acc[0]  = fmaf(ee, a0.x, acc[0]);  acc[1]  = fmaf(ee, a0.y, acc[1]);
            acc[2]  = fmaf(ee, a0.z, acc[2]);  acc[3]  = fmaf(ee, a0.w, acc[3]);
            acc[4]  = fmaf(ee, a1.x, acc[4]);  acc[5]  = fmaf(ee, a1.y, acc[5]);
            acc[6]  = fmaf(ee, a1.z, acc[6]);  acc[7]  = fmaf(ee, a1.w, acc[7]);
            acc[8]  = fmaf(ee, a2.x, acc[8]);  acc[9]  = fmaf(ee, a2.y, acc[9]);
            acc[10] = fmaf(ee, a2.z, acc[10]); acc[11] = fmaf(ee, a2.w, acc[11]);
            acc[12] = fmaf(ee, a3.x, acc[12]); acc[13] = fmaf(ee, a3.y, acc[13]);
            acc[14] = fmaf(ee, a3.z, acc[14]); acc[15] = fmaf(ee, a3.w, acc[15]);
            den += ee;
        }
        i += cnt;
    }
    // combine edge groups (same gl position across xor 8 / xor 16)
#pragma unroll
    for (int q = 0; q < 16; q++) {
        acc[q] += __shfl_xor_sync(0xffffffffu, acc[q], 8);
        acc[q] += __shfl_xor_sync(0xffffffffu, acc[q], 16);
    }
    den += __shfl_xor_sync(0xffffffffu, den, 8);
    den += __shfl_xor_sync(0xffffffffu, den, 16);

    if (g == 0) {
        float inv = 1.f / (den + EPS_DEN);   // per-head (gl subset holds its head's den)
        const float4* pb = (const float4*)(b1 + ch);
        float4 bb[4] = {pb[0], pb[1], pb[2], pb[3]};
        float o[16];
#pragma unroll
        for (int q = 0; q < 16; q++) {
            float b = (&bb[q >> 2].x)[q & 3];
            float v = acc[q] * inv + b;
            o[q] = v > 0.f ? v : expm1f(v);
        }
        __nv_bfloat16 hv[16], lv[16];
#pragma unroll
        for (int q = 0; q < 16; q++) {
            hv[q] = __float2bfloat16(o[q]);
            lv[q] = __float2bfloat16(o[q] - __bfloat162float(hv[q]));
        }
        uint4* ph = (uint4*)(g_ah + (size_t)node * 256 + ch);
        uint4* pl2 = (uint4*)(g_al + (size_t)node * 256 + ch);
        ph[0]  = ((const uint4*)hv)[0];  ph[1]  = ((const uint4*)hv)[1];
        pl2[0] = ((const uint4*)lv)[0];  pl2[1] = ((const uint4*)lv)[1];
    }
}

// ---------------- layer 2 aggregation: 4 edges/warp-iter ----------------
__global__ __launch_bounds__(256) void aggr2(const float* __restrict__ att,
                                             const float* __restrict__ b2,
                                             float* __restrict__ out) {
    int node = blockIdx.x * 8 + (threadIdx.x >> 5);
    if (node >= NNODES) return;
    int lane = threadIdx.x & 31;
    int g  = lane >> 3;
    int gl = lane & 7;
    int beg = g_row[node], end = g_row[node + 1];
    int ch = gl * 16;

    const float4* pr = (const float4*)(g_hr2 + (size_t)node * C2 + ch);
    float4 r0 = pr[0], r1 = pr[1], r2 = pr[2], r3 = pr[3];
    const float4* pa = (const float4*)(att + ch);
    float4 t0 = pa[0], t1 = pa[1], t2 = pa[2], t3 = pa[3];

    float acc[16];
#pragma unroll
    for (int q = 0; q < 16; q++) acc[q] = 0.f;
    float den = 0.f;

    int i = beg;
    while (i < end) {
        int cnt = min(32, end - i);
        int mysrc = __ldg(&g_srcs[i + min(lane, cnt - 1)]);
        for (int jb = 0; jb < cnt; jb += 4) {
            int idx = min(jb + g, cnt - 1);
            int src = __shfl_sync(0xffffffffu, mysrc, idx);
            bool valid = (jb + g) < cnt;
            const float4* pl = (const float4*)(g_hl2 + (size_t)src * C2 + ch);
            float4 a0 = __ldg(pl), a1 = __ldg(pl + 1), a2 = __ldg(pl + 2), a3 = __ldg(pl + 3);
            float s = lrelu(a0.x + r0.x) * t0.x + lrelu(a0.y + r0.y) * t0.y +
                      lrelu(a0.z + r0.z) * t0.z + lrelu(a0.w + r0.w) * t0.w +
                      lrelu(a1.x + r1.x) * t1.x + lrelu(a1.y + r1.y) * t1.y +
                      lrelu(a1.z + r1.z) * t1.z + lrelu(a1.w + r1.w) * t1.w +
                      lrelu(a2.x + r2.x) * t2.x + lrelu(a2.y + r2.y) * t2.y +
                      lrelu(a2.z + r2.z) * t2.z + lrelu(a2.w + r2.w) * t2.w +
                      lrelu(a3.x + r3.x) * t3.x + lrelu(a3.y + r3.y) * t3.y +
                      lrelu(a3.z + r3.z) * t3.z + lrelu(a3.w + r3.w) * t3.w;
            s += __shfl_xor_sync(0xffffffffu, s, 1);
            s += __shfl_xor_sync(0xffffffffu, s, 2);
            s += __shfl_xor_sync(0xffffffffu, s, 4);   // full 128-ch sum per group
            float ee = valid ? __expf(s) : 0.f;
            acc[0]  = fmaf(ee, a0.x, acc[0]);  acc[1]  = fmaf(ee, a0.y, acc[1]);
            acc[2]  = fmaf(ee, a0.z, acc[2]);  acc[3]  = fmaf(ee, a0.w, acc[3]);
            acc[4]  = fmaf(ee, a1.x, acc[4]);  acc[5]  = fmaf(ee, a1.y, acc[5]);
            acc[6]  = fmaf(ee, a1.z, acc[6]);  acc[7]  = fmaf(ee, a1.w, acc[7]);
            acc[8]  = fmaf(ee, a2.x, acc[8]);  acc[9]  = fmaf(ee, a2.y, acc[9]);
            acc[10] = fmaf(ee, a2.z, acc[10]); acc[11] = fmaf(ee, a2.w, acc[11]);
            acc[12] = fmaf(ee, a3.x, acc[12]); acc[13] = fmaf(ee, a3.y, acc[13]);
            acc[14] = fmaf(ee, a3.z, acc[14]); acc[15] = fmaf(ee, a3.w, acc[15]);
            den += ee;
        }
        i += cnt;
    }
#pragma unroll
    for (int q = 0; q < 16; q++) {
        acc[q] += __shfl_xor_sync(0xffffffffu, acc[q], 8);
        acc[q] += __shfl_xor_sync(0xffffffffu, acc[q], 16);
    }
    den += __shfl_xor_sync(0xffffffffu, den, 8);
    den += __shfl_xor_sync(0xffffffffu, den, 16);

    if (g == 0) {
        float inv = 1.f / (den + EPS_DEN);
        const float4* pb = (const float4*)(b2 + ch);
        float4 bb[4] = {pb[0], pb[1], pb[2], pb[3]};
        float4* po = (float4*)(out + (size_t)node * C2 + ch);
#pragma unroll
        for (int q = 0; q < 4; q++)
            po[q] = make_float4(acc[q*4+0] * inv + bb[q].x, acc[q*4+1] * inv + bb[q].y,
                                acc[q*4+2] * inv + bb[q].z, acc[q*4+3] * inv + bb[q].w);
    }
}

// ---------------- launch ----------------
extern "C" void kernel_launch(void* const* d_in, const int* in_sizes, int n_in,
                              void* d_out, int out_size) {
    const float* x    = (const float*)d_in[0];
    const int*   ei   = (const int*)d_in[1];
    const float* Wl1  = (const float*)d_in[2];
    const float* Wr1  = (const float*)d_in[3];
    const float* att1 = (const float*)d_in[4];
    const float* b1   = (const float*)d_in[5];
    const float* Wl2  = (const float*)d_in[6];
    const float* Wr2  = (const float*)d_in[7];
    const float* att2 = (const float*)d_in[8];
    const float* b2   = (const float*)d_in[9];
    float* out = (float*)d_out;

    float *xl1, *xr1, *hl2, *hr2;
    __nv_bfloat16 *ah, *al, *bhL, *blL, *bhR, *blR, *bhL2, *blL2, *bhR2, *blR2;
    cudaGetSymbolAddress((void**)&xl1, g_xl1);
    cudaGetSymbolAddress((void**)&xr1, g_xr1);
    cudaGetSymbolAddress((void**)&hl2, g_hl2);
    cudaGetSymbolAddress((void**)&hr2, g_hr2);
    cudaGetSymbolAddress((void**)&ah,  g_ah);
    cudaGetSymbolAddress((void**)&al,  g_al);
    cudaGetSymbolAddress((void**)&bhL, g_bhL);
    cudaGetSymbolAddress((void**)&blL, g_blL);
    cudaGetSymbolAddress((void**)&bhR, g_bhR);
    cudaGetSymbolAddress((void**)&blR, g_blR);
    cudaGetSymbolAddress((void**)&bhL2, g_bhL2);
    cudaGetSymbolAddress((void**)&blL2, g_blL2);
    cudaGetSymbolAddress((void**)&bhR2, g_bhR2);
    cudaGetSymbolAddress((void**)&blR2, g_blR2);

    const int T = 256;
    const int DSMEM = 73728;
    cudaFuncSetAttribute((const void*)mgemm<128, 128, 256>,
                         cudaFuncAttributeMaxDynamicSharedMemorySize, DSMEM);
    cudaFuncSetAttribute((const void*)mgemm<256, 256, 128>,
                         cudaFuncAttributeMaxDynamicSharedMemorySize, DSMEM);

    // side stream for CSR build (fork-join; capture-legal).
    cudaStream_t s2;
    cudaStreamCreateWithFlags(&s2, cudaStreamNonBlocking);
    cudaEvent_t evF, evJ;
    cudaEventCreateWithFlags(&evF, cudaEventDisableTiming);
    cudaEventCreateWithFlags(&evJ, cudaEventDisableTiming);

    cudaEventRecord(evF, 0);
    cudaStreamWaitEvent(s2, evF, 0);
    k_zero<<<(NNODES + T - 1) / T, T, 0, s2>>>();
    k_count<<<(NEDGES + T - 1) / T, T, 0, s2>>>(ei);
    k_scan<<<1, 1024, 0, s2>>>();
    k_fill<<<(NEDGES + T - 1) / T, T, 0, s2>>>(ei);
    cudaEventRecord(evJ, s2);

    // main stream: weight splits, input split, layer-1 dual GEMM
    k_splitw<<<(128 * 256 + T - 1) / T, T>>>(Wl1, bhL, blL, 128, 256);
    k_splitw<<<(128 * 256 + T - 1) / T, T>>>(Wr1, bhR, blR, 128, 256);
    k_splitw<<<(256 * 128 + T - 1) / T, T>>>(Wl2, bhL2, blL2, 256, 128);
    k_splitw<<<(256 * 128 + T - 1) / T, T>>>(Wr2, bhR2, blR2, 256, 128);
    k_split<<<(MPAD * 128 + T - 1) / T, T>>>(x, NNODES, 128);
    {
        dim3 grid(MPAD / 128, 4);
        mgemm<128, 128, 256><<<grid, 256, DSMEM>>>(ah, al, bhL, blL, bhR, blR, xl1, xr1);
    }

    // join: aggregation needs CSR + GEMM outputs
    cudaStreamWaitEvent(0, evJ, 0);

    int nblk = (NNODES + 7) / 8;
    aggr1h<<<nblk, 256>>>(att1, b1, 0);   // heads 0,1 (L2-resident pass)
    aggr1h<<<nblk, 256>>>(att1, b1, 1);   // heads 2,3

    // layer 2 dual GEMM (consumes g_ah/g_al written by aggr1h)
    {
        dim3 grid(MPAD / 128, 2);
        mgemm<256, 256, 128><<<grid, 256, DSMEM>>>(ah, al, bhL2, blL2, bhR2, blR2, hl2, hr2);
    }
    aggr2<<<nblk, 256>>>(att2, b2, out);
}

// round 12
// speedup vs baseline: 1.2549x; 1.2549x over previous
#include <cuda_runtime.h>
#include <cuda_bf16.h>
#include <cstdint>

#define NNODES 50000
#define NEDGES 800000
#define MPAD   50048      // 391 * 128
#define C1 256            // heads*hid layer1
#define C2 128            // out channels layer2
#define NEG_SLOPE 0.2f
#define EPS_DEN 1e-16f

// ---------------- scratch (device globals; no allocations allowed) ----------------
__device__ float g_xl1[NNODES * C1];
__device__ float g_xr1[NNODES * C1];
__device__ float g_hl2[NNODES * C2];
__device__ float g_hr2[NNODES * C2];
__device__ int   g_row[NNODES + 1];
__device__ int   g_cnt[NNODES];
__device__ int   g_srcs[NEDGES];
// bf16 split buffers
__device__ __align__(16) __nv_bfloat16 g_ah[MPAD * 256];
__device__ __align__(16) __nv_bfloat16 g_al[MPAD * 256];
__device__ __align__(16) __nv_bfloat16 g_bhL[32768];
__device__ __align__(16) __nv_bfloat16 g_blL[32768];
__device__ __align__(16) __nv_bfloat16 g_bhR[32768];
__device__ __align__(16) __nv_bfloat16 g_blR[32768];
__device__ __align__(16) __nv_bfloat16 g_bhL2[32768];
__device__ __align__(16) __nv_bfloat16 g_blL2[32768];
__device__ __align__(16) __nv_bfloat16 g_bhR2[32768];
__device__ __align__(16) __nv_bfloat16 g_blR2[32768];

// ---------------- helpers ----------------
__device__ __forceinline__ float lrelu(float x) { return x > 0.f ? x : NEG_SLOPE * x; }

__device__ __forceinline__ uint32_t smem_u32(const void* p) {
    uint32_t a;
    asm("{ .reg .u64 t; cvta.to.shared.u64 t, %1; cvt.u32.u64 %0, t; }" : "=r"(a) : "l"(p));
    return a;
}

__device__ __forceinline__ void ldsm_x4(uint32_t* r, uint32_t addr) {
    asm volatile("ldmatrix.sync.aligned.m8n8.x4.shared.b16 {%0,%1,%2,%3}, [%4];"
                 : "=r"(r[0]), "=r"(r[1]), "=r"(r[2]), "=r"(r[3]) : "r"(addr));
}

__device__ __forceinline__ void mma_bf16(float* c, const uint32_t* a,
                                         uint32_t b0, uint32_t b1) {
    asm volatile(
        "mma.sync.aligned.m16n8k16.row.col.f32.bf16.bf16.f32 "
        "{%0,%1,%2,%3}, {%4,%5,%6,%7}, {%8,%9}, {%0,%1,%2,%3};"
        : "+f"(c[0]), "+f"(c[1]), "+f"(c[2]), "+f"(c[3])
        : "r"(a[0]), "r"(a[1]), "r"(a[2]), "r"(a[3]), "r"(b0), "r"(b1));
}

#define CP_ASYNC16(dst, src) \
    asm volatile("cp.async.cg.shared.global [%0], [%1], 16;" :: "r"(dst), "l"(src))
#define CP_COMMIT() asm volatile("cp.async.commit_group;")
#define CP_WAIT1()  asm volatile("cp.async.wait_group 1;")
#define CP_WAIT0()  asm volatile("cp.async.wait_group 0;")

// ---------------- CSR build ----------------
__global__ void k_zero() {
    int i = blockIdx.x * blockDim.x + threadIdx.x;
    if (i < NNODES) g_cnt[i] = 0;
}
__global__ void k_count(const int* __restrict__ ei) {
    int e = blockIdx.x * blockDim.x + threadIdx.x;
    if (e < NEDGES) atomicAdd(&g_cnt[ei[NEDGES + e]], 1);
}
__global__ __launch_bounds__(1024) void k_scan() {
    __shared__ int s[1024];
    __shared__ int carry_s;
    int t = threadIdx.x;
    if (t == 0) carry_s = 0;
    __syncthreads();
    for (int base = 0; base < NNODES; base += 4096) {
        int idx = base + t * 4;
        int v0 = (idx + 0 < NNODES) ? g_cnt[idx + 0] : 0;
        int v1 = (idx + 1 < NNODES) ? g_cnt[idx + 1] : 0;
        int v2 = (idx + 2 < NNODES) ? g_cnt[idx + 2] : 0;
        int v3 = (idx + 3 < NNODES) ? g_cnt[idx + 3] : 0;
        int tot = v0 + v1 + v2 + v3;
        s[t] = tot;
        __syncthreads();
        for (int off = 1; off < 1024; off <<= 1) {
            int x = (t >= off) ? s[t - off] : 0;
            __syncthreads();
            s[t] += x;
            __syncthreads();
        }
        int excl = carry_s + s[t] - tot;
        if (idx + 0 < NNODES) { g_row[idx + 0] = excl;                g_cnt[idx + 0] = 0; }
        if (idx + 1 < NNODES) { g_row[idx + 1] = excl + v0;           g_cnt[idx + 1] = 0; }
        if (idx + 2 < NNODES) { g_row[idx + 2] = excl + v0 + v1;      g_cnt[idx + 2] = 0; }
        if (idx + 3 < NNODES) { g_row[idx + 3] = excl + v0 + v1 + v2; g_cnt[idx + 3] = 0; }
        __syncthreads();
        if (t == 1023) carry_s += s[1023];
        __syncthreads();
    }
    if (t == 0) g_row[NNODES] = NEDGES;
}
__global__ void k_fill(const int* __restrict__ ei) {
    int e = blockIdx.x * blockDim.x + threadIdx.x;
    if (e >= NEDGES) return;
    int dst = ei[NEDGES + e];
    int pos = g_row[dst] + atomicAdd(&g_cnt[dst], 1);
    g_srcs[pos] = ei[e];
}

// ---------------- bf16 hi/lo splits ----------------
__global__ void k_split(const float* __restrict__ A, int M, int K) {
    int i = blockIdx.x * blockDim.x + threadIdx.x;
    if (i >= MPAD * K) return;
    int m = i / K;
    float v = (m < M) ? A[i] : 0.f;
    __nv_bfloat16 h = __float2bfloat16(v);
    g_ah[i] = h;
    g_al[i] = __float2bfloat16(v - __bfloat162float(h));
}
// W [K x Nn] fp32 -> bh/bl [Nn x K] bf16 (transposed)
__global__ void k_splitw(const float* __restrict__ W, __nv_bfloat16* __restrict__ bh,
                         __nv_bfloat16* __restrict__ bl, int K, int Nn) {
    int i = blockIdx.x * blockDim.x + threadIdx.x;
    if (i >= K * Nn) return;
    int k = i / Nn, n = i - k * Nn;
    float v = W[i];
    __nv_bfloat16 h = __float2bfloat16(v);
    bh[n * K + k] = h;
    bl[n * K + k] = __float2bfloat16(v - __bfloat162float(h));
}

// ---------------- warp-MMA bf16x3 GEMM, cp.async double-buffered ------------------
// KS = row stride of A/B (elems); KT = K width. Full-K serial schedule.
template <int KS, int KT, int NPER>
__global__ __launch_bounds__(256) void mgemm(
    const __nv_bfloat16* __restrict__ Ah, const __nv_bfloat16* __restrict__ Al,
    const __nv_bfloat16* __restrict__ Bh0, const __nv_bfloat16* __restrict__ Bl0,
    const __nv_bfloat16* __restrict__ Bh1, const __nv_bfloat16* __restrict__ Bl1,
    float* __restrict__ Cd0, float* __restrict__ Cd1) {
    constexpr int KCH = KT / 64;
    constexpr int NCH = 3 * KCH;
    constexpr int NB  = NPER / 128;
    extern __shared__ char dsm[];

    const int tid = threadIdx.x, wid = tid >> 5, lane = tid & 31;
    const int mat  = blockIdx.y / NB;
    const int ncol = (blockIdx.y % NB) * 128;
    const __nv_bfloat16* Bh = mat ? Bh1 : Bh0;
    const __nv_bfloat16* Bl = mat ? Bl1 : Bl0;
    float* Cd = mat ? Cd1 : Cd0;
    const size_t blockM = (size_t)blockIdx.x * 128;

    const int wm = wid >> 1, wn = wid & 1;
    float acc[2][8][4];
#pragma unroll
    for (int mi = 0; mi < 2; mi++)
#pragma unroll
        for (int ni = 0; ni < 8; ni++)
#pragma unroll
            for (int q = 0; q < 4; q++) acc[mi][ni][q] = 0.f;

    const int a_r = (lane & 7) + ((lane >> 3) & 1) * 8;
    const int a_c = (lane >> 4) * 8;
    const int b_r = (lane & 7) + (lane >> 4) * 8;
    const int b_c = ((lane >> 3) & 1) * 8;

    auto issue = [&](int c, int s) {
        int seg = c / KCH;
        int kc = (c - seg * KCH) * 64;
        const __nv_bfloat16* Asrc = (seg == 2) ? Al : Ah;
        const __nv_bfloat16* Bsrc = (seg == 1) ? Bl : Bh;
        char* abase = dsm + s * 36864;
        char* bbase = abase + 18432;
#pragma unroll
        for (int u = tid; u < 1024; u += 256) {
            int r = u >> 3, j = u & 7;
            CP_ASYNC16(smem_u32(abase + r * 144 + j * 16),
                       Asrc + (blockM + r) * KS + kc + j * 8);
            CP_ASYNC16(smem_u32(bbase + r * 144 + j * 16),
                       Bsrc + (size_t)(ncol + r) * KS + kc + j * 8);
        }
        CP_COMMIT();
    };

    issue(0, 0);
    for (int c = 0; c < NCH; c++) {
        if (c + 1 < NCH) { issue(c + 1, (c + 1) & 1); CP_WAIT1(); }
        else             { CP_WAIT0(); }
        __syncthreads();
        char* abase = dsm + (c & 1) * 36864;
        char* bbase = abase + 18432;
#pragma unroll
        for (int ks = 0; ks < 4; ks++) {
            int k0 = ks * 16;
            uint32_t a[2][4];
#pragma unroll
            for (int mi = 0; mi < 2; mi++)
                ldsm_x4(a[mi], smem_u32(abase + (wm * 32 + mi * 16 + a_r) * 144 +
                                        (k0 + a_c) * 2));
            uint32_t b[4][4];
#pragma unroll
            for (int np = 0; np < 4; np++)
                ldsm_x4(b[np], smem_u32(bbase + (wn * 64 + np * 16 + b_r) * 144 +
                                        (k0 + b_c) * 2));
#pragma unroll
            for (int mi = 0; mi < 2; mi++)
#pragma unroll
                for (int ni = 0; ni < 8; ni++)
                    mma_bf16(acc[mi][ni], a[mi],
                             b[ni >> 1][(ni & 1) * 2], b[ni >> 1][(ni & 1) * 2 + 1]);
        }
        __syncthreads();
    }

#pragma unroll
    for (int mi = 0; mi < 2; mi++) {
        int r0 = (int)blockM + wm * 32 + mi * 16 + (lane >> 2);
#pragma unroll
        for (int ni = 0; ni < 8; ni++) {
            int col = ncol + wn * 64 + ni * 8 + (lane & 3) * 2;
            if (r0 < NNODES)
                *(float2*)&Cd[(size_t)r0 * NPER + col] =
                    make_float2(acc[mi][ni][0], acc[mi][ni][1]);
            if (r0 + 8 < NNODES)
                *(float2*)&Cd[(size_t)(r0 + 8) * NPER + col] =
                    make_float2(acc[mi][ni][2], acc[mi][ni][3]);
        }
    }
}

// ---------------- layer 1 aggregation: half heads, 2 edges/warp-iter --------------
// warp per node; lane = g*16 + gl; group g handles edge pair member g.
// gl covers 8 channels of [half*128, half*128+128); head = subgroup of 8 lanes.
// logit reduce: xor 1,2,4; group combine at end via xor 16.
// Source-index batches are software-pipelined (prefetch next batch).
__global__ __launch_bounds__(256) void aggr1h(const float* __restrict__ att,
                                              const float* __restrict__ b1,
                                              int half) {
    int node = blockIdx.x * 8 + (threadIdx.x >> 5);
    if (node >= NNODES) return;
    int lane = threadIdx.x & 31;
    int g  = lane >> 4;
    int gl = lane & 15;
    int beg = g_row[node], end = g_row[node + 1];
    int ch = half * 128 + gl * 8;

    const float4* pr = (const float4*)(g_xr1 + (size_t)node * C1 + ch);
    float4 r0 = pr[0], r1 = pr[1];
    const float4* pa = (const float4*)(att + ch);
    float4 t0 = pa[0], t1 = pa[1];

    float acc[8];
#pragma unroll
    for (int q = 0; q < 8; q++) acc[q] = 0.f;
    float den = 0.f;

    int i = beg;
    int cnt = min(32, end - i);
    int mysrc = (i < end) ? __ldg(&g_srcs[i + min(lane, cnt - 1)]) : 0;
    while (i < end) {
        // prefetch next batch's indices before processing this one
        int inext = i + cnt;
        int cnext = min(32, end - inext);
        int nsrc = (inext < end) ? __ldg(&g_srcs[inext + min(lane, cnext - 1)]) : 0;
        for (int jb = 0; jb < cnt; jb += 2) {
            int idx = min(jb + g, cnt - 1);
            int src = __shfl_sync(0xffffffffu, mysrc, idx);
            bool valid = (jb + g) < cnt;
            const float4* pl = (const float4*)(g_xl1 + (size_t)src * C1 + ch);
            float4 a0 = __ldg(pl), a1 = __ldg(pl + 1);
            float s = lrelu(a0.x + r0.x) * t0.x + lrelu(a0.y + r0.y) * t0.y +
                      lrelu(a0.z + r0.z) * t0.z + lrelu(a0.w + r0.w) * t0.w +
                      lrelu(a1.x + r1.x) * t1.x + lrelu(a1.y + r1.y) * t1.y +
                      lrelu(a1.z + r1.z) * t1.z + lrelu(a1.w + r1.w) * t1.w;
            s += __shfl_xor_sync(0xffffffffu, s, 1);
            s += __shfl_xor_sync(0xffffffffu, s, 2);
            s += __shfl_xor_sync(0xffffffffu, s, 4);
            float ee = valid ? __expf(s) : 0.f;
            acc[0] = fmaf(ee, a0.x, acc[0]);
            acc[1] = fmaf(ee, a0.y, acc[1]);
            acc[2] = fmaf(ee, a0.z, acc[2]);
            acc[3] = fmaf(ee, a0.w, acc[3]);
            acc[4] = fmaf(ee, a1.x, acc[4]);
            acc[5] = fmaf(ee, a1.y, acc[5]);
            acc[6] = fmaf(ee, a1.z, acc[6]);
            acc[7] = fmaf(ee, a1.w, acc[7]);
            den += ee;
        }
        i = inext;
        cnt = cnext;
        mysrc = nsrc;
    }
#pragma unroll
    for (int q = 0; q < 8; q++) acc[q] += __shfl_xor_sync(0xffffffffu, acc[q], 16);
    den += __shfl_xor_sync(0xffffffffu, den, 16);

    if (g == 0) {
        float inv = 1.f / (den + EPS_DEN);
        const float4* pb = (const float4*)(b1 + ch);
        float4 bb0 = pb[0], bb1 = pb[1];
        float o[8];
        o[0] = acc[0] * inv + bb0.x;  o[1] = acc[1] * inv + bb0.y;
        o[2] = acc[2] * inv + bb0.z;  o[3] = acc[3] * inv + bb0.w;
        o[4] = acc[4] * inv + bb1.x;  o[5] = acc[5] * inv + bb1.y;
        o[6] = acc[6] * inv + bb1.z;  o[7] = acc[7] * inv + bb1.w;
#pragma unroll
        for (int q = 0; q < 8; q++) o[q] = o[q] > 0.f ? o[q] : expm1f(o[q]);
        __nv_bfloat16 hv[8], lv[8];
#pragma unroll
        for (int q = 0; q < 8; q++) {
            hv[q] = __float2bfloat16(o[q]);
            lv[q] = __float2bfloat16(o[q] - __bfloat162float(hv[q]));
        }
        *(uint4*)(g_ah + (size_t)node * 256 + ch) = *(const uint4*)hv;
        *(uint4*)(g_al + (size_t)node * 256 + ch) = *(const uint4*)lv;
    }
}

// ---------------- layer 2 aggregation: 2 edges/warp-iter ----------------
__global__ __launch_bounds__(256) void aggr2(const float* __restrict__ att,
                                             const float* __restrict__ b2,
                                             float* __restrict__ out) {
    int node = blockIdx.x * 8 + (threadIdx.x >> 5);
    if (node >= NNODES) return;
    int lane = threadIdx.x & 31;
    int g  = lane >> 4;
    int gl = lane & 15;
    int beg = g_row[node], end = g_row[node + 1];
    int ch = gl * 8;

    const float4* pr = (const float4*)(g_hr2 + (size_t)node * C2 + ch);
    float4 r0 = pr[0], r1 = pr[1];
    const float4* pa = (const float4*)(att + ch);
    float4 t0 = pa[0], t1 = pa[1];

    float acc[8];
#pragma unroll
    for (int q = 0; q < 8; q++) acc[q] = 0.f;
    float den = 0.f;

    int i = beg;
    int cnt = min(32, end - i);
    int mysrc = (i < end) ? __ldg(&g_srcs[i + min(lane, cnt - 1)]) : 0;
    while (i < end) {
        int inext = i + cnt;
        int cnext = min(32, end - inext);
        int nsrc = (inext < end) ? __ldg(&g_srcs[inext + min(lane, cnext - 1)]) : 0;
        for (int jb = 0; jb < cnt; jb += 2) {
            int idx = min(jb + g, cnt - 1);
            int src = __shfl_sync(0xffffffffu, mysrc, idx);
            bool valid = (jb + g) < cnt;
            const float4* pl = (const float4*)(g_hl2 + (size_t)src * C2 + ch);
            float4 a0 = __ldg(pl), a1 = __ldg(pl + 1);
            float s = lrelu(a0.x + r0.x) * t0.x + lrelu(a0.y + r0.y) * t0.y +
                      lrelu(a0.z + r0.z) * t0.z + lrelu(a0.w + r0.w) * t0.w +
                      lrelu(a1.x + r1.x) * t1.x + lrelu(a1.y + r1.y) * t1.y +
                      lrelu(a1.z + r1.z) * t1.z + lrelu(a1.w + r1.w) * t1.w;
            s += __shfl_xor_sync(0xffffffffu, s, 1);
            s += __shfl_xor_sync(0xffffffffu, s, 2);
            s += __shfl_xor_sync(0xffffffffu, s, 4);
            s += __shfl_xor_sync(0xffffffffu, s, 8);
            float ee = valid ? __expf(s) : 0.f;
            acc[0] = fmaf(ee, a0.x, acc[0]);
            acc[1] = fmaf(ee, a0.y, acc[1]);
            acc[2] = fmaf(ee, a0.z, acc[2]);
            acc[3] = fmaf(ee, a0.w, acc[3]);
            acc[4] = fmaf(ee, a1.x, acc[4]);
            acc[5] = fmaf(ee, a1.y, acc[5]);
            acc[6] = fmaf(ee, a1.z, acc[6]);
            acc[7] = fmaf(ee, a1.w, acc[7]);
            den += ee;
        }
        i = inext;
        cnt = cnext;
        mysrc = nsrc;
    }
#pragma unroll
    for (int q = 0; q < 8; q++) acc[q] += __shfl_xor_sync(0xffffffffu, acc[q], 16);
    den += __shfl_xor_sync(0xffffffffu, den, 16);

    if (g == 0) {
        float inv = 1.f / (den + EPS_DEN);
        const float4* pb = (const float4*)(b2 + ch);
        float4 bb0 = pb[0], bb1 = pb[1];
        float4* po = (float4*)(out + (size_t)node * C2 + ch);
        po[0] = make_float4(acc[0] * inv + bb0.x, acc[1] * inv + bb0.y,
                            acc[2] * inv + bb0.z, acc[3] * inv + bb0.w);
        po[1] = make_float4(acc[4] * inv + bb1.x, acc[5] * inv + bb1.y,
                            acc[6] * inv + bb1.z, acc[7] * inv + bb1.w);
    }
}

// ---------------- launch ----------------
extern "C" void kernel_launch(void* const* d_in, const int* in_sizes, int n_in,
                              void* d_out, int out_size) {
    const float* x    = (const float*)d_in[0];
    const int*   ei   = (const int*)d_in[1];
    const float* Wl1  = (const float*)d_in[2];
    const float* Wr1  = (const float*)d_in[3];
    const float* att1 = (const float*)d_in[4];
    const float* b1   = (const float*)d_in[5];
    const float* Wl2  = (const float*)d_in[6];
    const float* Wr2  = (const float*)d_in[7];
    const float* att2 = (const float*)d_in[8];
    const float* b2   = (const float*)d_in[9];
    float* out = (float*)d_out;

    float *xl1, *xr1, *hl2, *hr2;
    __nv_bfloat16 *ah, *al, *bhL, *blL, *bhR, *blR, *bhL2, *blL2, *bhR2, *blR2;
    cudaGetSymbolAddress((void**)&xl1, g_xl1);
    cudaGetSymbolAddress((void**)&xr1, g_xr1);
    cudaGetSymbolAddress((void**)&hl2, g_hl2);
    cudaGetSymbolAddress((void**)&hr2, g_hr2);
    cudaGetSymbolAddress((void**)&ah,  g_ah);
    cudaGetSymbolAddress((void**)&al,  g_al);
    cudaGetSymbolAddress((void**)&bhL, g_bhL);
    cudaGetSymbolAddress((void**)&blL, g_blL);
    cudaGetSymbolAddress((void**)&bhR, g_bhR);
    cudaGetSymbolAddress((void**)&blR, g_blR);
    cudaGetSymbolAddress((void**)&bhL2, g_bhL2);
    cudaGetSymbolAddress((void**)&blL2, g_blL2);
    cudaGetSymbolAddress((void**)&bhR2, g_bhR2);
    cudaGetSymbolAddress((void**)&blR2, g_blR2);

    const int T = 256;
    const int DSMEM = 73728;
    cudaFuncSetAttribute((const void*)mgemm<128, 128, 256>,
                         cudaFuncAttributeMaxDynamicSharedMemorySize, DSMEM);
    cudaFuncSetAttribute((const void*)mgemm<256, 256, 128>,
                         cudaFuncAttributeMaxDynamicSharedMemorySize, DSMEM);

    // side stream for CSR build (fork-join; capture-legal).
    cudaStream_t s2;
    cudaStreamCreateWithFlags(&s2, cudaStreamNonBlocking);
    cudaEvent_t evF, evJ;
    cudaEventCreateWithFlags(&evF, cudaEventDisableTiming);
    cudaEventCreateWithFlags(&evJ, cudaEventDisableTiming);

    cudaEventRecord(evF, 0);
    cudaStreamWaitEvent(s2, evF, 0);
    k_zero<<<(NNODES + T - 1) / T, T, 0, s2>>>();
    k_count<<<(NEDGES + T - 1) / T, T, 0, s2>>>(ei);
    k_scan<<<1, 1024, 0, s2>>>();
    k_fill<<<(NEDGES + T - 1) / T, T, 0, s2>>>(ei);
    cudaEventRecord(evJ, s2);

    // main stream: weight splits, input split, layer-1 dual GEMM
    k_splitw<<<(128 * 256 + T - 1) / T, T>>>(Wl1, bhL, blL, 128, 256);
    k_splitw<<<(128 * 256 + T - 1) / T, T>>>(Wr1, bhR, blR, 128, 256);
    k_splitw<<<(256 * 128 + T - 1) / T, T>>>(Wl2, bhL2, blL2, 256, 128);
    k_splitw<<<(256 * 128 + T - 1) / T, T>>>(Wr2, bhR2, blR2, 256, 128);
    k_split<<<(MPAD * 128 + T - 1) / T, T>>>(x, NNODES, 128);
    {
        dim3 grid(MPAD / 128, 4);
        mgemm<128, 128, 256><<<grid, 256, DSMEM>>>(ah, al, bhL, blL, bhR, blR, xl1, xr1);
    }

    // join: aggregation needs CSR + GEMM outputs
    cudaStreamWaitEvent(0, evJ, 0);

    int nblk = (NNODES + 7) / 8;
    aggr1h<<<nblk, 256>>>(att1, b1, 0);   // heads 0,1 (L2-resident pass)
    aggr1h<<<nblk, 256>>>(att1, b1, 1);   // heads 2,3

    // layer 2 dual GEMM (consumes g_ah/g_al written by aggr1h)
    {
        dim3 grid(MPAD / 128, 2);
        mgemm<256, 256, 128><<<grid, 256, DSMEM>>>(ah, al, bhL2, blL2, bhR2, blR2, hl2, hr2);
    }
    aggr2<<<nblk, 256>>>(att2, b2, out);
}

// round 13
// speedup vs baseline: 1.3551x; 1.0798x over previous
#include <cuda_runtime.h>
#include <cuda_bf16.h>
#include <cstdint>

#define NNODES 50000
#define NEDGES 800000
#define MPAD   50048      // 391 * 128
#define C1 256            // heads*hid layer1
#define C2 128            // out channels layer2
#define NEG_SLOPE 0.2f
#define EPS_DEN 1e-16f

// ---------------- scratch (device globals; no allocations allowed) ----------------
__device__ float g_xl1[NNODES * C1];
__device__ float g_xr1[NNODES * C1];
__device__ float g_hl2[NNODES * C2];
__device__ float g_hr2[NNODES * C2];
__device__ int   g_row[NNODES + 1];
__device__ int   g_cnt[NNODES];
__device__ int   g_srcs[NEDGES];
// bf16 split buffers
__device__ __align__(16) __nv_bfloat16 g_ah[MPAD * 256];
__device__ __align__(16) __nv_bfloat16 g_al[MPAD * 256];
__device__ __align__(16) __nv_bfloat16 g_bhL[32768];
__device__ __align__(16) __nv_bfloat16 g_blL[32768];
__device__ __align__(16) __nv_bfloat16 g_bhR[32768];
__device__ __align__(16) __nv_bfloat16 g_blR[32768];
__device__ __align__(16) __nv_bfloat16 g_bhL2[32768];
__device__ __align__(16) __nv_bfloat16 g_blL2[32768];
__device__ __align__(16) __nv_bfloat16 g_bhR2[32768];
__device__ __align__(16) __nv_bfloat16 g_blR2[32768];

// ---------------- helpers ----------------
__device__ __forceinline__ float lrelu(float x) { return x > 0.f ? x : NEG_SLOPE * x; }

__device__ __forceinline__ uint32_t smem_u32(const void* p) {
    uint32_t a;
    asm("{ .reg .u64 t; cvta.to.shared.u64 t, %1; cvt.u32.u64 %0, t; }" : "=r"(a) : "l"(p));
    return a;
}

__device__ __forceinline__ void ldsm_x4(uint32_t* r, uint32_t addr) {
    asm volatile("ldmatrix.sync.aligned.m8n8.x4.shared.b16 {%0,%1,%2,%3}, [%4];"
                 : "=r"(r[0]), "=r"(r[1]), "=r"(r[2]), "=r"(r[3]) : "r"(addr));
}

__device__ __forceinline__ void mma_bf16(float* c, const uint32_t* a,
                                         uint32_t b0, uint32_t b1) {
    asm volatile(
        "mma.sync.aligned.m16n8k16.row.col.f32.bf16.bf16.f32 "
        "{%0,%1,%2,%3}, {%4,%5,%6,%7}, {%8,%9}, {%0,%1,%2,%3};"
        : "+f"(c[0]), "+f"(c[1]), "+f"(c[2]), "+f"(c[3])
        : "r"(a[0]), "r"(a[1]), "r"(a[2]), "r"(a[3]), "r"(b0), "r"(b1));
}

#define CP_ASYNC16(dst, src) \
    asm volatile("cp.async.cg.shared.global [%0], [%1], 16;" :: "r"(dst), "l"(src))
#define CP_COMMIT() asm volatile("cp.async.commit_group;")
#define CP_WAIT1()  asm volatile("cp.async.wait_group 1;")
#define CP_WAIT0()  asm volatile("cp.async.wait_group 0;")

// ---------------- CSR build ----------------
__global__ void k_zero() {
    int i = blockIdx.x * blockDim.x + threadIdx.x;
    if (i < NNODES) g_cnt[i] = 0;
}
__global__ void k_count(const int* __restrict__ ei) {
    int e = blockIdx.x * blockDim.x + threadIdx.x;
    if (e < NEDGES) atomicAdd(&g_cnt[ei[NEDGES + e]], 1);
}
__global__ __launch_bounds__(1024) void k_scan() {
    __shared__ int s[1024];
    __shared__ int carry_s;
    int t = threadIdx.x;
    if (t == 0) carry_s = 0;
    __syncthreads();
    for (int base = 0; base < NNODES; base += 4096) {
        int idx = base + t * 4;
        int v0 = (idx + 0 < NNODES) ? g_cnt[idx + 0] : 0;
        int v1 = (idx + 1 < NNODES) ? g_cnt[idx + 1] : 0;
        int v2 = (idx + 2 < NNODES) ? g_cnt[idx + 2] : 0;
        int v3 = (idx + 3 < NNODES) ? g_cnt[idx + 3] : 0;
        int tot = v0 + v1 + v2 + v3;
        s[t] = tot;
        __syncthreads();
        for (int off = 1; off < 1024; off <<= 1) {
            int x = (t >= off) ? s[t - off] : 0;
            __syncthreads();
            s[t] += x;
            __syncthreads();
        }
        int excl = carry_s + s[t] - tot;
        if (idx + 0 < NNODES) { g_row[idx + 0] = excl;                g_cnt[idx + 0] = 0; }
        if (idx + 1 < NNODES) { g_row[idx + 1] = excl + v0;           g_cnt[idx + 1] = 0; }
        if (idx + 2 < NNODES) { g_row[idx + 2] = excl + v0 + v1;      g_cnt[idx + 2] = 0; }
        if (idx + 3 < NNODES) { g_row[idx + 3] = excl + v0 + v1 + v2; g_cnt[idx + 3] = 0; }
        __syncthreads();
        if (t == 1023) carry_s += s[1023];
        __syncthreads();
    }
    if (t == 0) g_row[NNODES] = NEDGES;
}
__global__ void k_fill(const int* __restrict__ ei) {
    int e = blockIdx.x * blockDim.x + threadIdx.x;
    if (e >= NEDGES) return;
    int dst = ei[NEDGES + e];
    int pos = g_row[dst] + atomicAdd(&g_cnt[dst], 1);
    g_srcs[pos] = ei[e];
}

// ---------------- bf16 hi/lo splits ----------------
__global__ void k_split(const float* __restrict__ A, int M, int K) {
    int i = blockIdx.x * blockDim.x + threadIdx.x;
    if (i >= MPAD * K) return;
    int m = i / K;
    float v = (m < M) ? A[i] : 0.f;
    __nv_bfloat16 h = __float2bfloat16(v);
    g_ah[i] = h;
    g_al[i] = __float2bfloat16(v - __bfloat162float(h));
}

// all four weight splits in one launch. Segments of 32768 elements each:
// 0: Wl1 (K=128,Nn=256) -> g_bhL/g_blL     1: Wr1 -> g_bhR/g_blR
// 2: Wl2 (K=256,Nn=128) -> g_bhL2/g_blL2   3: Wr2 -> g_bhR2/g_blR2
__global__ void k_splitw4(const float* __restrict__ Wl1, const float* __restrict__ Wr1,
                          const float* __restrict__ Wl2, const float* __restrict__ Wr2) {
    int i = blockIdx.x * blockDim.x + threadIdx.x;
    if (i >= 4 * 32768) return;
    int seg = i >> 15;
    int j = i & 32767;
    const float* W;
    __nv_bfloat16 *bh, *bl;
    int K, Nn;
    if (seg == 0)      { W = Wl1; bh = g_bhL;  bl = g_blL;  K = 128; Nn = 256; }
    else if (seg == 1) { W = Wr1; bh = g_bhR;  bl = g_blR;  K = 128; Nn = 256; }
    else if (seg == 2) { W = Wl2; bh = g_bhL2; bl = g_blL2; K = 256; Nn = 128; }
    else               { W = Wr2; bh = g_bhR2; bl = g_blR2; K = 256; Nn = 128; }
    int k = j / Nn, n = j - k * Nn;
    float v = W[j];
    __nv_bfloat16 h = __float2bfloat16(v);
    bh[n * K + k] = h;
    bl[n * K + k] = __float2bfloat16(v - __bfloat162float(h));
}

// ---------------- warp-MMA bf16x3 GEMM, cp.async double-buffered ------------------
// KS = row stride of A/B (elems); KT = K width. Full-K serial schedule.
template <int KS, int KT, int NPER>
__global__ __launch_bounds__(256) void mgemm(
    const __nv_bfloat16* __restrict__ Ah, const __nv_bfloat16* __restrict__ Al,
    const __nv_bfloat16* __restrict__ Bh0, const __nv_bfloat16* __restrict__ Bl0,
    const __nv_bfloat16* __restrict__ Bh1, const __nv_bfloat16* __restrict__ Bl1,
    float* __restrict__ Cd0, float* __restrict__ Cd1) {
    constexpr int KCH = KT / 64;
    constexpr int NCH = 3 * KCH;
    constexpr int NB  = NPER / 128;
    extern __shared__ char dsm[];

    const int tid = threadIdx.x, wid = tid >> 5, lane = tid & 31;
    const int mat  = blockIdx.y / NB;
    const int ncol = (blockIdx.y % NB) * 128;
    const __nv_bfloat16* Bh = mat ? Bh1 : Bh0;
    const __nv_bfloat16* Bl = mat ? Bl1 : Bl0;
    float* Cd = mat ? Cd1 : Cd0;
    const size_t blockM = (size_t)blockIdx.x * 128;

    const int wm = wid >> 1, wn = wid & 1;
    float acc[2][8][4];
#pragma unroll
    for (int mi = 0; mi < 2; mi++)
#pragma unroll
        for (int ni = 0; ni < 8; ni++)
#pragma unroll
            for (int q = 0; q < 4; q++) acc[mi][ni][q] = 0.f;

    const int a_r = (lane & 7) + ((lane >> 3) & 1) * 8;
    const int a_c = (lane >> 4) * 8;
    const int b_r = (lane & 7) + (lane >> 4) * 8;
    const int b_c = ((lane >> 3) & 1) * 8;

    auto issue = [&](int c, int s) {
        int seg = c / KCH;
        int kc = (c - seg * KCH) * 64;
        const __nv_bfloat16* Asrc = (seg == 2) ? Al : Ah;
        const __nv_bfloat16* Bsrc = (seg == 1) ? Bl : Bh;
        char* abase = dsm + s * 36864;
        char* bbase = abase + 18432;
#pragma unroll
        for (int u = tid; u < 1024; u += 256) {
            int r = u >> 3, j = u & 7;
            CP_ASYNC16(smem_u32(abase + r * 144 + j * 16),
                       Asrc + (blockM + r) * KS + kc + j * 8);
            CP_ASYNC16(smem_u32(bbase + r * 144 + j * 16),
                       Bsrc + (size_t)(ncol + r) * KS + kc + j * 8);
        }
        CP_COMMIT();
    };

    issue(0, 0);
    for (int c = 0; c < NCH; c++) {
        if (c + 1 < NCH) { issue(c + 1, (c + 1) & 1); CP_WAIT1(); }
        else             { CP_WAIT0(); }
        __syncthreads();
        char* abase = dsm + (c & 1) * 36864;
        char* bbase = abase + 18432;
#pragma unroll
        for (int ks = 0; ks < 4; ks++) {
            int k0 = ks * 16;
            uint32_t a[2][4];
#pragma unroll
            for (int mi = 0; mi < 2; mi++)
                ldsm_x4(a[mi], smem_u32(abase + (wm * 32 + mi * 16 + a_r) * 144 +
                                        (k0 + a_c) * 2));
            uint32_t b[4][4];
#pragma unroll
            for (int np = 0; np < 4; np++)
                ldsm_x4(b[np], smem_u32(bbase + (wn * 64 + np * 16 + b_r) * 144 +
                                        (k0 + b_c) * 2));
#pragma unroll
            for (int mi = 0; mi < 2; mi++)
#pragma unroll
                for (int ni = 0; ni < 8; ni++)
                    mma_bf16(acc[mi][ni], a[mi],
                             b[ni >> 1][(ni & 1) * 2], b[ni >> 1][(ni & 1) * 2 + 1]);
        }
        __syncthreads();
    }

#pragma unroll
    for (int mi = 0; mi < 2; mi++) {
        int r0 = (int)blockM + wm * 32 + mi * 16 + (lane >> 2);
#pragma unroll
        for (int ni = 0; ni < 8; ni++) {
            int col = ncol + wn * 64 + ni * 8 + (lane & 3) * 2;
            if (r0 < NNODES)
                *(float2*)&Cd[(size_t)r0 * NPER + col] =
                    make_float2(acc[mi][ni][0], acc[mi][ni][1]);
            if (r0 + 8 < NNODES)
                *(float2*)&Cd[(size_t)(r0 + 8) * NPER + col] =
                    make_float2(acc[mi][ni][2], acc[mi][ni][3]);
        }
    }
}

// ---------------- layer 1 aggregation: half heads, 2 edges/warp-iter --------------
// warp per node; lane = g*16 + gl; group g handles edge pair member g.
// gl covers 8 channels of [half*128, half*128+128); head = subgroup of 8 lanes.
// logit reduce: xor 1,2,4; group combine at end via xor 16.
__global__ __launch_bounds__(256) void aggr1h(const float* __restrict__ att,
                                              const float* __restrict__ b1,
                                              int half) {
    int node = blockIdx.x * 8 + (threadIdx.x >> 5);
    if (node >= NNODES) return;
    int lane = threadIdx.x & 31;
    int g  = lane >> 4;
    int gl = lane & 15;
    int beg = g_row[node], end = g_row[node + 1];
    int ch = half * 128 + gl * 8;

    const float4* pr = (const float4*)(g_xr1 + (size_t)node * C1 + ch);
    float4 r0 = pr[0], r1 = pr[1];
    const float4* pa = (const float4*)(att + ch);
    float4 t0 = pa[0], t1 = pa[1];

    float acc[8];
#pragma unroll
    for (int q = 0; q < 8; q++) acc[q] = 0.f;
    float den = 0.f;

    int i = beg;
    while (i < end) {
        int cnt = min(32, end - i);
        int mysrc = __ldg(&g_srcs[i + min(lane, cnt - 1)]);
        for (int jb = 0; jb < cnt; jb += 2) {
            int idx = min(jb + g, cnt - 1);
            int src = __shfl_sync(0xffffffffu, mysrc, idx);
            bool valid = (jb + g) < cnt;
            const float4* pl = (const float4*)(g_xl1 + (size_t)src * C1 + ch);
            float4 a0 = __ldg(pl), a1 = __ldg(pl + 1);
            float s = lrelu(a0.x + r0.x) * t0.x + lrelu(a0.y + r0.y) * t0.y +
                      lrelu(a0.z + r0.z) * t0.z + lrelu(a0.w + r0.w) * t0.w +
                      lrelu(a1.x + r1.x) * t1.x + lrelu(a1.y + r1.y) * t1.y +
                      lrelu(a1.z + r1.z) * t1.z + lrelu(a1.w + r1.w) * t1.w;
            s += __shfl_xor_sync(0xffffffffu, s, 1);
            s += __shfl_xor_sync(0xffffffffu, s, 2);
            s += __shfl_xor_sync(0xffffffffu, s, 4);
            float ee = valid ? __expf(s) : 0.f;
            acc[0] = fmaf(ee, a0.x, acc[0]);
            acc[1] = fmaf(ee, a0.y, acc[1]);
            acc[2] = fmaf(ee, a0.z, acc[2]);
            acc[3] = fmaf(ee, a0.w, acc[3]);
            acc[4] = fmaf(ee, a1.x, acc[4]);
            acc[5] = fmaf(ee, a1.y, acc[5]);
            acc[6] = fmaf(ee, a1.z, acc[6]);
            acc[7] = fmaf(ee, a1.w, acc[7]);
            den += ee;
        }
        i += cnt;
    }
#pragma unroll
    for (int q = 0; q < 8; q++) acc[q] += __shfl_xor_sync(0xffffffffu, acc[q], 16);
    den += __shfl_xor_sync(0xffffffffu, den, 16);

    if (g == 0) {
        float inv = 1.f / (den + EPS_DEN);
        const float4* pb = (const float4*)(b1 + ch);
        float4 bb0 = pb[0], bb1 = pb[1];
        float o[8];
        o[0] = acc[0] * inv + bb0.x;  o[1] = acc[1] * inv + bb0.y;
        o[2] = acc[2] * inv + bb0.z;  o[3] = acc[3] * inv + bb0.w;
        o[4] = acc[4] * inv + bb1.x;  o[5] = acc[5] * inv + bb1.y;
        o[6] = acc[6] * inv + bb1.z;  o[7] = acc[7] * inv + bb1.w;
#pragma unroll
        for (int q = 0; q < 8; q++) o[q] = o[q] > 0.f ? o[q] : expm1f(o[q]);
        __nv_bfloat16 hv[8], lv[8];
#pragma unroll
        for (int q = 0; q < 8; q++) {
            hv[q] = __float2bfloat16(o[q]);
            lv[q] = __float2bfloat16(o[q] - __bfloat162float(hv[q]));
        }
        *(uint4*)(g_ah + (size_t)node * 256 + ch) = *(const uint4*)hv;
        *(uint4*)(g_al + (size_t)node * 256 + ch) = *(const uint4*)lv;
    }
}

// ---------------- layer 2 aggregation: 2 edges/warp-iter ----------------
__global__ __launch_bounds__(256) void aggr2(const float* __restrict__ att,
                                             const float* __restrict__ b2,
                                             float* __restrict__ out) {
    int node = blockIdx.x * 8 + (threadIdx.x >> 5);
    if (node >= NNODES) return;
    int lane = threadIdx.x & 31;
    int g  = lane >> 4;
    int gl = lane & 15;
    int beg = g_row[node], end = g_row[node + 1];
    int ch = gl * 8;

    const float4* pr = (const float4*)(g_hr2 + (size_t)node * C2 + ch);
    float4 r0 = pr[0], r1 = pr[1];
    const float4* pa = (const float4*)(att + ch);
    float4 t0 = pa[0], t1 = pa[1];

    float acc[8];
#pragma unroll
    for (int q = 0; q < 8; q++) acc[q] = 0.f;
    float den = 0.f;

    int i = beg;
    while (i < end) {
        int cnt = min(32, end - i);
        int mysrc = __ldg(&g_srcs[i + min(lane, cnt - 1)]);
        for (int jb = 0; jb < cnt; jb += 2) {
            int idx = min(jb + g, cnt - 1);
            int src = __shfl_sync(0xffffffffu, mysrc, idx);
            bool valid = (jb + g) < cnt;
            const float4* pl = (const float4*)(g_hl2 + (size_t)src * C2 + ch);
            float4 a0 = __ldg(pl), a1 = __ldg(pl + 1);
            float s = lrelu(a0.x + r0.x) * t0.x + lrelu(a0.y + r0.y) * t0.y +
                      lrelu(a0.z + r0.z) * t0.z + lrelu(a0.w + r0.w) * t0.w +
                      lrelu(a1.x + r1.x) * t1.x + lrelu(a1.y + r1.y) * t1.y +
                      lrelu(a1.z + r1.z) * t1.z + lrelu(a1.w + r1.w) * t1.w;
            s += __shfl_xor_sync(0xffffffffu, s, 1);
            s += __shfl_xor_sync(0xffffffffu, s, 2);
            s += __shfl_xor_sync(0xffffffffu, s, 4);
            s += __shfl_xor_sync(0xffffffffu, s, 8);
            float ee = valid ? __expf(s) : 0.f;
            acc[0] = fmaf(ee, a0.x, acc[0]);
            acc[1] = fmaf(ee, a0.y, acc[1]);
            acc[2] = fmaf(ee, a0.z, acc[2]);
            acc[3] = fmaf(ee, a0.w, acc[3]);
            acc[4] = fmaf(ee, a1.x, acc[4]);
            acc[5] = fmaf(ee, a1.y, acc[5]);
            acc[6] = fmaf(ee, a1.z, acc[6]);
            acc[7] = fmaf(ee, a1.w, acc[7]);
            den += ee;
        }
        i += cnt;
    }
#pragma unroll
    for (int q = 0; q < 8; q++) acc[q] += __shfl_xor_sync(0xffffffffu, acc[q], 16);
    den += __shfl_xor_sync(0xffffffffu, den, 16);

    if (g == 0) {
        float inv = 1.f / (den + EPS_DEN);
        const float4* pb = (const float4*)(b2 + ch);
        float4 bb0 = pb[0], bb1 = pb[1];
        float4* po = (float4*)(out + (size_t)node * C2 + ch);
        po[0] = make_float4(acc[0] * inv + bb0.x, acc[1] * inv + bb0.y,
                            acc[2] * inv + bb0.z, acc[3] * inv + bb0.w);
        po[1] = make_float4(acc[4] * inv + bb1.x, acc[5] * inv + bb1.y,
                            acc[6] * inv + bb1.z, acc[7] * inv + bb1.w);
    }
}

// ---------------- launch ----------------
extern "C" void kernel_launch(void* const* d_in, const int* in_sizes, int n_in,
                              void* d_out, int out_size) {
    const float* x    = (const float*)d_in[0];
    const int*   ei   = (const int*)d_in[1];
    const float* Wl1  = (const float*)d_in[2];
    const float* Wr1  = (const float*)d_in[3];
    const float* att1 = (const float*)d_in[4];
    const float* b1   = (const float*)d_in[5];
    const float* Wl2  = (const float*)d_in[6];
    const float* Wr2  = (const float*)d_in[7];
    const float* att2 = (const float*)d_in[8];
    const float* b2   = (const float*)d_in[9];
    float* out = (float*)d_out;

    float *xl1, *xr1, *hl2, *hr2;
    __nv_bfloat16 *ah, *al, *bhL, *blL, *bhR, *blR, *bhL2, *blL2, *bhR2, *blR2;
    cudaGetSymbolAddress((void**)&xl1, g_xl1);
    cudaGetSymbolAddress((void**)&xr1, g_xr1);
    cudaGetSymbolAddress((void**)&hl2, g_hl2);
    cudaGetSymbolAddress((void**)&hr2, g_hr2);
    cudaGetSymbolAddress((void**)&ah,  g_ah);
    cudaGetSymbolAddress((void**)&al,  g_al);
    cudaGetSymbolAddress((void**)&bhL, g_bhL);
    cudaGetSymbolAddress((void**)&blL, g_blL);
    cudaGetSymbolAddress((void**)&bhR, g_bhR);
    cudaGetSymbolAddress((void**)&blR, g_blR);
    cudaGetSymbolAddress((void**)&bhL2, g_bhL2);
    cudaGetSymbolAddress((void**)&blL2, g_blL2);
    cudaGetSymbolAddress((void**)&bhR2, g_bhR2);
    cudaGetSymbolAddress((void**)&blR2, g_blR2);

    const int T = 256;
    const int DSMEM = 73728;
    cudaFuncSetAttribute((const void*)mgemm<128, 128, 256>,
                         cudaFuncAttributeMaxDynamicSharedMemorySize, DSMEM);
    cudaFuncSetAttribute((const void*)mgemm<256, 256, 128>,
                         cudaFuncAttributeMaxDynamicSharedMemorySize, DSMEM);

    // side stream for CSR build (fork-join; capture-legal).
    cudaStream_t s2;
    cudaStreamCreateWithFlags(&s2, cudaStreamNonBlocking);
    cudaEvent_t evF, evJ;
    cudaEventCreateWithFlags(&evF, cudaEventDisableTiming);
    cudaEventCreateWithFlags(&evJ, cudaEventDisableTiming);

    cudaEventRecord(evF, 0);
    cudaStreamWaitEvent(s2, evF, 0);
    k_zero<<<(NNODES + T - 1) / T, T, 0, s2>>>();
    k_count<<<(NEDGES + T - 1) / T, T, 0, s2>>>(ei);
    k_scan<<<1, 1024, 0, s2>>>();
    k_fill<<<(NEDGES + T - 1) / T, T, 0, s2>>>(ei);
    cudaEventRecord(evJ, s2);

    // main stream: merged weight split, input split, layer-1 dual GEMM
    k_splitw4<<<(4 * 32768 + T - 1) / T, T>>>(Wl1, Wr1, Wl2, Wr2);
    k_split<<<(MPAD * 128 + T - 1) / T, T>>>(x, NNODES, 128);
    {
        dim3 grid(MPAD / 128, 4);
        mgemm<128, 128, 256><<<grid, 256, DSMEM>>>(ah, al, bhL, blL, bhR, blR, xl1, xr1);
    }

    // join: aggregation needs CSR + GEMM outputs
    cudaStreamWaitEvent(0, evJ, 0);

    int nblk = (NNODES + 7) / 8;
    aggr1h<<<nblk, 256>>>(att1, b1, 0);   // heads 0,1 (L2-resident pass)
    aggr1h<<<nblk, 256>>>(att1, b1, 1);   // heads 2,3

    // layer 2 dual GEMM (consumes g_ah/g_al written by aggr1h)
    {
        dim3 grid(MPAD / 128, 2);
        mgemm<256, 256, 128><<<grid, 256, DSMEM>>>(ah, al, bhL2, blL2, bhR2, blR2, hl2, hr2);
    }
    aggr2<<<nblk, 256>>>(att2, b2, out);
}

// round 14
// speedup vs baseline: 1.4095x; 1.0402x over previous
#include <cuda_runtime.h>
#include <cuda_fp16.h>
#include <cstdint>

#define NNODES 50000
#define NEDGES 800000
#define MPAD   50048      // 391 * 128
#define C1 256            // heads*hid layer1
#define C2 128            // out channels layer2
#define NEG_SLOPE 0.2f
#define EPS_DEN 1e-16f

// ---------------- scratch (device globals; no allocations allowed) ----------------
__device__ float g_xl1[NNODES * C1];
__device__ float g_xr1[NNODES * C1];
__device__ float g_hl2[NNODES * C2];
__device__ float g_hr2[NNODES * C2];
__device__ int   g_row[NNODES + 1];
__device__ int   g_cnt[NNODES];
__device__ int   g_srcs[NEDGES];
// fp16 split buffers
__device__ __align__(16) __half g_ah[MPAD * 256];
__device__ __align__(16) __half g_al[MPAD * 256];
__device__ __align__(16) __half g_bhL[32768];
__device__ __align__(16) __half g_blL[32768];
__device__ __align__(16) __half g_bhR[32768];
__device__ __align__(16) __half g_blR[32768];
__device__ __align__(16) __half g_bhL2[32768];
__device__ __align__(16) __half g_blL2[32768];
__device__ __align__(16) __half g_bhR2[32768];
__device__ __align__(16) __half g_blR2[32768];

// ---------------- helpers ----------------
__device__ __forceinline__ float lrelu(float x) { return x > 0.f ? x : NEG_SLOPE * x; }

__device__ __forceinline__ uint32_t smem_u32(const void* p) {
    uint32_t a;
    asm("{ .reg .u64 t; cvta.to.shared.u64 t, %1; cvt.u32.u64 %0, t; }" : "=r"(a) : "l"(p));
    return a;
}

__device__ __forceinline__ void ldsm_x4(uint32_t* r, uint32_t addr) {
    asm volatile("ldmatrix.sync.aligned.m8n8.x4.shared.b16 {%0,%1,%2,%3}, [%4];"
                 : "=r"(r[0]), "=r"(r[1]), "=r"(r[2]), "=r"(r[3]) : "r"(addr));
}

__device__ __forceinline__ void mma_f16(float* c, const uint32_t* a,
                                        uint32_t b0, uint32_t b1) {
    asm volatile(
        "mma.sync.aligned.m16n8k16.row.col.f32.f16.f16.f32 "
        "{%0,%1,%2,%3}, {%4,%5,%6,%7}, {%8,%9}, {%0,%1,%2,%3};"
        : "+f"(c[0]), "+f"(c[1]), "+f"(c[2]), "+f"(c[3])
        : "r"(a[0]), "r"(a[1]), "r"(a[2]), "r"(a[3]), "r"(b0), "r"(b1));
}

#define CP_ASYNC16(dst, src) \
    asm volatile("cp.async.cg.shared.global [%0], [%1], 16;" :: "r"(dst), "l"(src))
#define CP_COMMIT() asm volatile("cp.async.commit_group;")
#define CP_WAIT1()  asm volatile("cp.async.wait_group 1;")
#define CP_WAIT0()  asm volatile("cp.async.wait_group 0;")

// ---------------- CSR build ----------------
__global__ void k_zero() {
    int i = blockIdx.x * blockDim.x + threadIdx.x;
    if (i < NNODES) g_cnt[i] = 0;
}
__global__ void k_count(const int* __restrict__ ei) {
    int e = blockIdx.x * blockDim.x + threadIdx.x;
    if (e < NEDGES) atomicAdd(&g_cnt[ei[NEDGES + e]], 1);
}
__global__ __launch_bounds__(1024) void k_scan() {
    __shared__ int s[1024];
    __shared__ int carry_s;
    int t = threadIdx.x;
    if (t == 0) carry_s = 0;
    __syncthreads();
    for (int base = 0; base < NNODES; base += 4096) {
        int idx = base + t * 4;
        int v0 = (idx + 0 < NNODES) ? g_cnt[idx + 0] : 0;
        int v1 = (idx + 1 < NNODES) ? g_cnt[idx + 1] : 0;
        int v2 = (idx + 2 < NNODES) ? g_cnt[idx + 2] : 0;
        int v3 = (idx + 3 < NNODES) ? g_cnt[idx + 3] : 0;
        int tot = v0 + v1 + v2 + v3;
        s[t] = tot;
        __syncthreads();
        for (int off = 1; off < 1024; off <<= 1) {
            int x = (t >= off) ? s[t - off] : 0;
            __syncthreads();
            s[t] += x;
            __syncthreads();
        }
        int excl = carry_s + s[t] - tot;
        if (idx + 0 < NNODES) { g_row[idx + 0] = excl;                g_cnt[idx + 0] = 0; }
        if (idx + 1 < NNODES) { g_row[idx + 1] = excl + v0;           g_cnt[idx + 1] = 0; }
        if (idx + 2 < NNODES) { g_row[idx + 2] = excl + v0 + v1;      g_cnt[idx + 2] = 0; }
        if (idx + 3 < NNODES) { g_row[idx + 3] = excl + v0 + v1 + v2; g_cnt[idx + 3] = 0; }
        __syncthreads();
        if (t == 1023) carry_s += s[1023];
        __syncthreads();
    }
    if (t == 0) g_row[NNODES] = NEDGES;
}
__global__ void k_fill(const int* __restrict__ ei) {
    int e = blockIdx.x * blockDim.x + threadIdx.x;
    if (e >= NEDGES) return;
    int dst = ei[NEDGES + e];
    int pos = g_row[dst] + atomicAdd(&g_cnt[dst], 1);
    g_srcs[pos] = ei[e];
}

// ---------------- fp16 hi/lo splits ----------------
__global__ void k_split(const float* __restrict__ A, int M, int K) {
    int i = blockIdx.x * blockDim.x + threadIdx.x;
    if (i >= MPAD * K) return;
    int m = i / K;
    float v = (m < M) ? A[i] : 0.f;
    __half h = __float2half_rn(v);
    g_ah[i] = h;
    g_al[i] = __float2half_rn(v - __half2float(h));
}

// all four weight splits in one launch. Segments of 32768 elements each.
__global__ void k_splitw4(const float* __restrict__ Wl1, const float* __restrict__ Wr1,
                          const float* __restrict__ Wl2, const float* __restrict__ Wr2) {
    int i = blockIdx.x * blockDim.x + threadIdx.x;
    if (i >= 4 * 32768) return;
    int seg = i >> 15;
    int j = i & 32767;
    const float* W;
    __half *bh, *bl;
    int K, Nn;
    if (seg == 0)      { W = Wl1; bh = g_bhL;  bl = g_blL;  K = 128; Nn = 256; }
    else if (seg == 1) { W = Wr1; bh = g_bhR;  bl = g_blR;  K = 128; Nn = 256; }
    else if (seg == 2) { W = Wl2; bh = g_bhL2; bl = g_blL2; K = 256; Nn = 128; }
    else               { W = Wr2; bh = g_bhR2; bl = g_blR2; K = 256; Nn = 128; }
    int k = j / Nn, n = j - k * Nn;
    float v = W[j];
    __half h = __float2half_rn(v);
    bh[n * K + k] = h;
    bl[n * K + k] = __float2half_rn(v - __half2float(h));
}

// ---------------- warp-MMA fp16 GEMM, cp.async double-buffered --------------------
// KS = row stride of A/B (elems); KT = K width.
// TERMS=3: Ah*Bh + Ah*Bl + Al*Bh (full precision, err ~2^-22)
// TERMS=2: Ah*Bh + Al*Bh (B single fp16; err ~2^-11 random-walk)
template <int KS, int KT, int NPER, int TERMS>
__global__ __launch_bounds__(256) void mgemm(
    const __half* __restrict__ Ah, const __half* __restrict__ Al,
    const __half* __restrict__ Bh0, const __half* __restrict__ Bl0,
    const __half* __restrict__ Bh1, const __half* __restrict__ Bl1,
    float* __restrict__ Cd0, float* __restrict__ Cd1) {
    constexpr int KCH = KT / 64;
    constexpr int NCH = TERMS * KCH;
    constexpr int NB  = NPER / 128;
    extern __shared__ char dsm[];

    const int tid = threadIdx.x, wid = tid >> 5, lane = tid & 31;
    const int mat  = blockIdx.y / NB;
    const int ncol = (blockIdx.y % NB) * 128;
    const __half* Bh = mat ? Bh1 : Bh0;
    const __half* Bl = mat ? Bl1 : Bl0;
    float* Cd = mat ? Cd1 : Cd0;
    const size_t blockM = (size_t)blockIdx.x * 128;

    const int wm = wid >> 1, wn = wid & 1;
    float acc[2][8][4];
#pragma unroll
    for (int mi = 0; mi < 2; mi++)
#pragma unroll
        for (int ni = 0; ni < 8; ni++)
#pragma unroll
            for (int q = 0; q < 4; q++) acc[mi][ni][q] = 0.f;

    const int a_r = (lane & 7) + ((lane >> 3) & 1) * 8;
    const int a_c = (lane >> 4) * 8;
    const int b_r = (lane & 7) + (lane >> 4) * 8;
    const int b_c = ((lane >> 3) & 1) * 8;

    auto issue = [&](int c, int s) {
        int seg = c / KCH;
        int kc = (c - seg * KCH) * 64;
        const __half* Asrc;
        const __half* Bsrc;
        if (TERMS == 3) {
            Asrc = (seg == 2) ? Al : Ah;
            Bsrc = (seg == 1) ? Bl : Bh;
        } else {
            Asrc = (seg == 1) ? Al : Ah;
            Bsrc = Bh;
        }
        char* abase = dsm + s * 36864;
        char* bbase = abase + 18432;
#pragma unroll
        for (int u = tid; u < 1024; u += 256) {
            int r = u >> 3, j = u & 7;
            CP_ASYNC16(smem_u32(abase + r * 144 + j * 16),
                       Asrc + (blockM + r) * KS + kc + j * 8);
            CP_ASYNC16(smem_u32(bbase + r * 144 + j * 16),
                       Bsrc + (size_t)(ncol + r) * KS + kc + j * 8);
        }
        CP_COMMIT();
    };

    issue(0, 0);
    for (int c = 0; c < NCH; c++) {
        if (c + 1 < NCH) { issue(c + 1, (c + 1) & 1); CP_WAIT1(); }
        else             { CP_WAIT0(); }
        __syncthreads();
        char* abase = dsm + (c & 1) * 36864;
        char* bbase = abase + 18432;
#pragma unroll
        for (int ks = 0; ks < 4; ks++) {
            int k0 = ks * 16;
            uint32_t a[2][4];
#pragma unroll
            for (int mi = 0; mi < 2; mi++)
                ldsm_x4(a[mi], smem_u32(abase + (wm * 32 + mi * 16 + a_r) * 144 +
                                        (k0 + a_c) * 2));
            uint32_t b[4][4];
#pragma unroll
            for (int np = 0; np < 4; np++)
                ldsm_x4(b[np], smem_u32(bbase + (wn * 64 + np * 16 + b_r) * 144 +
                                        (k0 + b_c) * 2));
#pragma unroll
            for (int mi = 0; mi < 2; mi++)
#pragma unroll
                for (int ni = 0; ni < 8; ni++)
                    mma_f16(acc[mi][ni], a[mi],
                            b[ni >> 1][(ni & 1) * 2], b[ni >> 1][(ni & 1) * 2 + 1]);
        }
        __syncthreads();
    }

#pragma unroll
    for (int mi = 0; mi < 2; mi++) {
        int r0 = (int)blockM + wm * 32 + mi * 16 + (lane >> 2);
#pragma unroll
        for (int ni = 0; ni < 8; ni++) {
            int col = ncol + wn * 64 + ni * 8 + (lane & 3) * 2;
            if (r0 < NNODES)
                *(float2*)&Cd[(size_t)r0 * NPER + col] =
                    make_float2(acc[mi][ni][0], acc[mi][ni][1]);
            if (r0 + 8 < NNODES)
                *(float2*)&Cd[(size_t)(r0 + 8) * NPER + col] =
                    make_float2(acc[mi][ni][2], acc[mi][ni][3]);
        }
    }
}

// ---------------- layer 1 aggregation: half heads, 2 edges/warp-iter --------------
// warp per node; lane = g*16 + gl; group g handles edge pair member g.
// gl covers 8 channels of [half*128, half*128+128); head = subgroup of 8 lanes.
// logit reduce: xor 1,2,4; group combine at end via xor 16.
__global__ __launch_bounds__(256) void aggr1h(const float* __restrict__ att,
                                              const float* __restrict__ b1,
                                              int half) {
    int node = blockIdx.x * 8 + (threadIdx.x >> 5);
    if (node >= NNODES) return;
    int lane = threadIdx.x & 31;
    int g  = lane >> 4;
    int gl = lane & 15;
    int beg = g_row[node], end = g_row[node + 1];
    int ch = half * 128 + gl * 8;

    const float4* pr = (const float4*)(g_xr1 + (size_t)node * C1 + ch);
    float4 r0 = pr[0], r1 = pr[1];
    const float4* pa = (const float4*)(att + ch);
    float4 t0 = pa[0], t1 = pa[1];

    float acc[8];
#pragma unroll
    for (int q = 0; q < 8; q++) acc[q] = 0.f;
    float den = 0.f;

    int i = beg;
    while (i < end) {
        int cnt = min(32, end - i);
        int mysrc = __ldg(&g_srcs[i + min(lane, cnt - 1)]);
        for (int jb = 0; jb < cnt; jb += 2) {
            int idx = min(jb + g, cnt - 1);
            int src = __shfl_sync(0xffffffffu, mysrc, idx);
            bool valid = (jb + g) < cnt;
            const float4* pl = (const float4*)(g_xl1 + (size_t)src * C1 + ch);
            float4 a0 = __ldg(pl), a1 = __ldg(pl + 1);
            float s = lrelu(a0.x + r0.x) * t0.x + lrelu(a0.y + r0.y) * t0.y +
                      lrelu(a0.z + r0.z) * t0.z + lrelu(a0.w + r0.w) * t0.w +
                      lrelu(a1.x + r1.x) * t1.x + lrelu(a1.y + r1.y) * t1.y +
                      lrelu(a1.z + r1.z) * t1.z + lrelu(a1.w + r1.w) * t1.w;
            s += __shfl_xor_sync(0xffffffffu, s, 1);
            s += __shfl_xor_sync(0xffffffffu, s, 2);
            s += __shfl_xor_sync(0xffffffffu, s, 4);
            float ee = valid ? __expf(s) : 0.f;
            acc[0] = fmaf(ee, a0.x, acc[0]);
            acc[1] = fmaf(ee, a0.y, acc[1]);
            acc[2] = fmaf(ee, a0.z, acc[2]);
            acc[3] = fmaf(ee, a0.w, acc[3]);
            acc[4] = fmaf(ee, a1.x, acc[4]);
            acc[5] = fmaf(ee, a1.y, acc[5]);
            acc[6] = fmaf(ee, a1.z, acc[6]);
            acc[7] = fmaf(ee, a1.w, acc[7]);
            den += ee;
        }
        i += cnt;
    }
#pragma unroll
    for (int q = 0; q < 8; q++) acc[q] += __shfl_xor_sync(0xffffffffu, acc[q], 16);
    den += __shfl_xor_sync(0xffffffffu, den, 16);

    if (g == 0) {
        float inv = 1.f / (den + EPS_DEN);
        const float4* pb = (const float4*)(b1 + ch);
        float4 bb0 = pb[0], bb1 = pb[1];
        float o[8];
        o[0] = acc[0] * inv + bb0.x;  o[1] = acc[1] * inv + bb0.y;
        o[2] = acc[2] * inv + bb0.z;  o[3] = acc[3] * inv + bb0.w;
        o[4] = acc[4] * inv + bb1.x;  o[5] = acc[5] * inv + bb1.y;
        o[6] = acc[6] * inv + bb1.z;  o[7] = acc[7] * inv + bb1.w;
#pragma unroll
        for (int q = 0; q < 8; q++) o[q] = o[q] > 0.f ? o[q] : expm1f(o[q]);
        __half hv[8], lv[8];
#pragma unroll
        for (int q = 0; q < 8; q++) {
            hv[q] = __float2half_rn(o[q]);
            lv[q] = __float2half_rn(o[q] - __half2float(hv[q]));
        }
        *(uint4*)(g_ah + (size_t)node * 256 + ch) = *(const uint4*)hv;
        *(uint4*)(g_al + (size_t)node * 256 + ch) = *(const uint4*)lv;
    }
}

// ---------------- layer 2 aggregation: 2 edges/warp-iter ----------------
__global__ __launch_bounds__(256) void aggr2(const float* __restrict__ att,
                                             const float* __restrict__ b2,
                                             float* __restrict__ out) {
    int node = blockIdx.x * 8 + (threadIdx.x >> 5);
    if (node >= NNODES) return;
    int lane = threadIdx.x & 31;
    int g  = lane >> 4;
    int gl = lane & 15;
    int beg = g_row[node], end = g_row[node + 1];
    int ch = gl * 8;

    const float4* pr = (const float4*)(g_hr2 + (size_t)node * C2 + ch);
    float4 r0 = pr[0], r1 = pr[1];
    const float4* pa = (const float4*)(att + ch);
    float4 t0 = pa[0], t1 = pa[1];

    float acc[8];
#pragma unroll
    for (int q = 0; q < 8; q++) acc[q] = 0.f;
    float den = 0.f;

    int i = beg;
    while (i < end) {
        int cnt = min(32, end - i);
        int mysrc = __ldg(&g_srcs[i + min(lane, cnt - 1)]);
        for (int jb = 0; jb < cnt; jb += 2) {
            int idx = min(jb + g, cnt - 1);
            int src = __shfl_sync(0xffffffffu, mysrc, idx);
            bool valid = (jb + g) < cnt;
            const float4* pl = (const float4*)(g_hl2 + (size_t)src * C2 + ch);
            float4 a0 = __ldg(pl), a1 = __ldg(pl + 1);
            float s = lrelu(a0.x + r0.x) * t0.x + lrelu(a0.y + r0.y) * t0.y +
                      lrelu(a0.z + r0.z) * t0.z + lrelu(a0.w + r0.w) * t0.w +
                      lrelu(a1.x + r1.x) * t1.x + lrelu(a1.y + r1.y) * t1.y +
                      lrelu(a1.z + r1.z) * t1.z + lrelu(a1.w + r1.w) * t1.w;
            s += __shfl_xor_sync(0xffffffffu, s, 1);
            s += __shfl_xor_sync(0xffffffffu, s, 2);
            s += __shfl_xor_sync(0xffffffffu, s, 4);
            s += __shfl_xor_sync(0xffffffffu, s, 8);
            float ee = valid ? __expf(s) : 0.f;
            acc[0] = fmaf(ee, a0.x, acc[0]);
            acc[1] = fmaf(ee, a0.y, acc[1]);
            acc[2] = fmaf(ee, a0.z, acc[2]);
            acc[3] = fmaf(ee, a0.w, acc[3]);
            acc[4] = fmaf(ee, a1.x, acc[4]);
            acc[5] = fmaf(ee, a1.y, acc[5]);
            acc[6] = fmaf(ee, a1.z, acc[6]);
            acc[7] = fmaf(ee, a1.w, acc[7]);
            den += ee;
        }
        i += cnt;
    }
#pragma unroll
    for (int q = 0; q < 8; q++) acc[q] += __shfl_xor_sync(0xffffffffu, acc[q], 16);
    den += __shfl_xor_sync(0xffffffffu, den, 16);

    if (g == 0) {
        float inv = 1.f / (den + EPS_DEN);
        const float4* pb = (const float4*)(b2 + ch);
        float4 bb0 = pb[0], bb1 = pb[1];
        float4* po = (float4*)(out + (size_t)node * C2 + ch);
        po[0] = make_float4(acc[0] * inv + bb0.x, acc[1] * inv + bb0.y,
                            acc[2] * inv + bb0.z, acc[3] * inv + bb0.w);
        po[1] = make_float4(acc[4] * inv + bb1.x, acc[5] * inv + bb1.y,
                            acc[6] * inv + bb1.z, acc[7] * inv + bb1.w);
    }
}

// ---------------- launch ----------------
extern "C" void kernel_launch(void* const* d_in, const int* in_sizes, int n_in,
                              void* d_out, int out_size) {
    const float* x    = (const float*)d_in[0];
    const int*   ei   = (const int*)d_in[1];
    const float* Wl1  = (const float*)d_in[2];
    const float* Wr1  = (const float*)d_in[3];
    const float* att1 = (const float*)d_in[4];
    const float* b1   = (const float*)d_in[5];
    const float* Wl2  = (const float*)d_in[6];
    const float* Wr2  = (const float*)d_in[7];
    const float* att2 = (const float*)d_in[8];
    const float* b2   = (const float*)d_in[9];
    float* out = (float*)d_out;

    float *xl1, *xr1, *hl2, *hr2;
    __half *ah, *al, *bhL, *blL, *bhR, *blR, *bhL2, *blL2, *bhR2, *blR2;
    cudaGetSymbolAddress((void**)&xl1, g_xl1);
    cudaGetSymbolAddress((void**)&xr1, g_xr1);
    cudaGetSymbolAddress((void**)&hl2, g_hl2);
    cudaGetSymbolAddress((void**)&hr2, g_hr2);
    cudaGetSymbolAddress((void**)&ah,  g_ah);
    cudaGetSymbolAddress((void**)&al,  g_al);
    cudaGetSymbolAddress((void**)&bhL, g_bhL);
    cudaGetSymbolAddress((void**)&blL, g_blL);
    cudaGetSymbolAddress((void**)&bhR, g_bhR);
    cudaGetSymbolAddress((void**)&blR, g_blR);
    cudaGetSymbolAddress((void**)&bhL2, g_bhL2);
    cudaGetSymbolAddress((void**)&blL2, g_blL2);
    cudaGetSymbolAddress((void**)&bhR2, g_bhR2);
    cudaGetSymbolAddress((void**)&blR2, g_blR2);

    const int T = 256;
    const int DSMEM = 73728;
    cudaFuncSetAttribute((const void*)mgemm<128, 128, 256, 2>,
                         cudaFuncAttributeMaxDynamicSharedMemorySize, DSMEM);
    cudaFuncSetAttribute((const void*)mgemm<256, 256, 128, 3>,
                         cudaFuncAttributeMaxDynamicSharedMemorySize, DSMEM);

    // side stream for CSR build (fork-join; capture-legal).
    cudaStream_t s2;
    cudaStreamCreateWithFlags(&s2, cudaStreamNonBlocking);
    cudaEvent_t evF, evJ;
    cudaEventCreateWithFlags(&evF, cudaEventDisableTiming);
    cudaEventCreateWithFlags(&evJ, cudaEventDisableTiming);

    cudaEventRecord(evF, 0);
    cudaStreamWaitEvent(s2, evF, 0);
    k_zero<<<(NNODES + T - 1) / T, T, 0, s2>>>();
    k_count<<<(NEDGES + T - 1) / T, T, 0, s2>>>(ei);
    k_scan<<<1, 1024, 0, s2>>>();
    k_fill<<<(NEDGES + T - 1) / T, T, 0, s2>>>(ei);
    cudaEventRecord(evJ, s2);

    // main stream: merged weight split, input split, layer-1 dual GEMM (2-term)
    k_splitw4<<<(4 * 32768 + T - 1) / T, T>>>(Wl1, Wr1, Wl2, Wr2);
    k_split<<<(MPAD * 128 + T - 1) / T, T>>>(x, NNODES, 128);
    {
        dim3 grid(MPAD / 128, 4);
        mgemm<128, 128, 256, 2><<<grid, 256, DSMEM>>>(ah, al, bhL, blL, bhR, blR,
                                                      xl1, xr1);
    }

    // join: aggregation needs CSR + GEMM outputs
    cudaStreamWaitEvent(0, evJ, 0);

    int nblk = (NNODES + 7) / 8;
    aggr1h<<<nblk, 256>>>(att1, b1, 0);   // heads 0,1 (L2-resident pass)
    aggr1h<<<nblk, 256>>>(att1, b1, 1);   // heads 2,3

    // layer 2 dual GEMM (3-term fp16; consumes g_ah/g_al written by aggr1h)
    {
        dim3 grid(MPAD / 128, 2);
        mgemm<256, 256, 128, 3><<<grid, 256, DSMEM>>>(ah, al, bhL2, blL2, bhR2, blR2,
                                                      hl2, hr2);
    }
    aggr2<<<nblk, 256>>>(att2, b2, out);
}

// round 15
// speedup vs baseline: 1.4987x; 1.0632x over previous
#include <cuda_runtime.h>
#include <cuda_fp16.h>
#include <cstdint>

#define NNODES 50000
#define NEDGES 800000
#define MPAD   50048      // 391 * 128
#define C1 256            // heads*hid layer1
#define C2 128            // out channels layer2
#define NEG_SLOPE 0.2f
#define EPS_DEN 1e-16f

// ---------------- scratch (device globals; no allocations allowed) ----------------
__device__ float g_xl1[NNODES * C1];
__device__ float g_xr1[NNODES * C1];
__device__ float g_hl2[NNODES * C2];
__device__ float g_hr2[NNODES * C2];
__device__ int   g_row[NNODES + 1];
__device__ int   g_cnt[NNODES];
__device__ int   g_srcs[NEDGES];
// fp16 split buffers
__device__ __align__(16) __half g_ah[MPAD * 256];
__device__ __align__(16) __half g_al[MPAD * 256];
__device__ __align__(16) __half g_bhL[32768];
__device__ __align__(16) __half g_blL[32768];
__device__ __align__(16) __half g_bhR[32768];
__device__ __align__(16) __half g_blR[32768];
__device__ __align__(16) __half g_bhL2[32768];
__device__ __align__(16) __half g_blL2[32768];
__device__ __align__(16) __half g_bhR2[32768];
__device__ __align__(16) __half g_blR2[32768];

// ---------------- helpers ----------------
__device__ __forceinline__ float lrelu(float x) { return x > 0.f ? x : NEG_SLOPE * x; }

__device__ __forceinline__ uint32_t smem_u32(const void* p) {
    uint32_t a;
    asm("{ .reg .u64 t; cvta.to.shared.u64 t, %1; cvt.u32.u64 %0, t; }" : "=r"(a) : "l"(p));
    return a;
}

__device__ __forceinline__ void ldsm_x4(uint32_t* r, uint32_t addr) {
    asm volatile("ldmatrix.sync.aligned.m8n8.x4.shared.b16 {%0,%1,%2,%3}, [%4];"
                 : "=r"(r[0]), "=r"(r[1]), "=r"(r[2]), "=r"(r[3]) : "r"(addr));
}

__device__ __forceinline__ void mma_f16(float* c, const uint32_t* a,
                                        uint32_t b0, uint32_t b1) {
    asm volatile(
        "mma.sync.aligned.m16n8k16.row.col.f32.f16.f16.f32 "
        "{%0,%1,%2,%3}, {%4,%5,%6,%7}, {%8,%9}, {%0,%1,%2,%3};"
        : "+f"(c[0]), "+f"(c[1]), "+f"(c[2]), "+f"(c[3])
        : "r"(a[0]), "r"(a[1]), "r"(a[2]), "r"(a[3]), "r"(b0), "r"(b1));
}

#define CP_ASYNC16(dst, src) \
    asm volatile("cp.async.cg.shared.global [%0], [%1], 16;" :: "r"(dst), "l"(src))
#define CP_COMMIT() asm volatile("cp.async.commit_group;")
#define CP_WAIT1()  asm volatile("cp.async.wait_group 1;")
#define CP_WAIT0()  asm volatile("cp.async.wait_group 0;")

// ---------------- CSR build ----------------
__global__ void k_zero() {
    int i = blockIdx.x * blockDim.x + threadIdx.x;
    if (i < NNODES) g_cnt[i] = 0;
}
__global__ void k_count(const int* __restrict__ ei) {
    int e = blockIdx.x * blockDim.x + threadIdx.x;
    if (e < NEDGES) atomicAdd(&g_cnt[ei[NEDGES + e]], 1);
}
__global__ __launch_bounds__(1024) void k_scan() {
    __shared__ int s[1024];
    __shared__ int carry_s;
    int t = threadIdx.x;
    if (t == 0) carry_s = 0;
    __syncthreads();
    for (int base = 0; base < NNODES; base += 4096) {
        int idx = base + t * 4;
        int v0 = (idx + 0 < NNODES) ? g_cnt[idx + 0] : 0;
        int v1 = (idx + 1 < NNODES) ? g_cnt[idx + 1] : 0;
        int v2 = (idx + 2 < NNODES) ? g_cnt[idx + 2] : 0;
        int v3 = (idx + 3 < NNODES) ? g_cnt[idx + 3] : 0;
        int tot = v0 + v1 + v2 + v3;
        s[t] = tot;
        __syncthreads();
        for (int off = 1; off < 1024; off <<= 1) {
            int x = (t >= off) ? s[t - off] : 0;
            __syncthreads();
            s[t] += x;
            __syncthreads();
        }
        int excl = carry_s + s[t] - tot;
        if (idx + 0 < NNODES) { g_row[idx + 0] = excl;                g_cnt[idx + 0] = 0; }
        if (idx + 1 < NNODES) { g_row[idx + 1] = excl + v0;           g_cnt[idx + 1] = 0; }
        if (idx + 2 < NNODES) { g_row[idx + 2] = excl + v0 + v1;      g_cnt[idx + 2] = 0; }
        if (idx + 3 < NNODES) { g_row[idx + 3] = excl + v0 + v1 + v2; g_cnt[idx + 3] = 0; }
        __syncthreads();
        if (t == 1023) carry_s += s[1023];
        __syncthreads();
    }
    if (t == 0) g_row[NNODES] = NEDGES;
}
__global__ void k_fill(const int* __restrict__ ei) {
    int e = blockIdx.x * blockDim.x + threadIdx.x;
    if (e >= NEDGES) return;
    int dst = ei[NEDGES + e];
    int pos = g_row[dst] + atomicAdd(&g_cnt[dst], 1);
    g_srcs[pos] = ei[e];
}

// ---------------- fp16 hi/lo splits ----------------
__global__ void k_split(const float* __restrict__ A, int M, int K) {
    int i = blockIdx.x * blockDim.x + threadIdx.x;
    if (i >= MPAD * K) return;
    int m = i / K;
    float v = (m < M) ? A[i] : 0.f;
    __half h = __float2half_rn(v);
    g_ah[i] = h;
    g_al[i] = __float2half_rn(v - __half2float(h));
}

// all four weight splits in one launch. Segments of 32768 elements each.
__global__ void k_splitw4(const float* __restrict__ Wl1, const float* __restrict__ Wr1,
                          const float* __restrict__ Wl2, const float* __restrict__ Wr2) {
    int i = blockIdx.x * blockDim.x + threadIdx.x;
    if (i >= 4 * 32768) return;
    int seg = i >> 15;
    int j = i & 32767;
    const float* W;
    __half *bh, *bl;
    int K, Nn;
    if (seg == 0)      { W = Wl1; bh = g_bhL;  bl = g_blL;  K = 128; Nn = 256; }
    else if (seg == 1) { W = Wr1; bh = g_bhR;  bl = g_blR;  K = 128; Nn = 256; }
    else if (seg == 2) { W = Wl2; bh = g_bhL2; bl = g_blL2; K = 256; Nn = 128; }
    else               { W = Wr2; bh = g_bhR2; bl = g_blR2; K = 256; Nn = 128; }
    int k = j / Nn, n = j - k * Nn;
    float v = W[j];
    __half h = __float2half_rn(v);
    bh[n * K + k] = h;
    bl[n * K + k] = __float2half_rn(v - __half2float(h));
}

// ---------------- warp-MMA fp16 GEMM, cp.async double-buffered --------------------
// KS = row stride of A/B (elems); KT = K width.
// TERMS=3: Ah*Bh + Ah*Bl + Al*Bh (full precision, err ~2^-22)
// TERMS=2: Ah*Bh + Al*Bh (B single fp16; err ~2^-11 random-walk)
template <int KS, int KT, int NPER, int TERMS>
__global__ __launch_bounds__(256) void mgemm(
    const __half* __restrict__ Ah, const __half* __restrict__ Al,
    const __half* __restrict__ Bh0, const __half* __restrict__ Bl0,
    const __half* __restrict__ Bh1, const __half* __restrict__ Bl1,
    float* __restrict__ Cd0, float* __restrict__ Cd1) {
    constexpr int KCH = KT / 64;
    constexpr int NCH = TERMS * KCH;
    constexpr int NB  = NPER / 128;
    extern __shared__ char dsm[];

    const int tid = threadIdx.x, wid = tid >> 5, lane = tid & 31;
    const int mat  = blockIdx.y / NB;
    const int ncol = (blockIdx.y % NB) * 128;
    const __half* Bh = mat ? Bh1 : Bh0;
    const __half* Bl = mat ? Bl1 : Bl0;
    float* Cd = mat ? Cd1 : Cd0;
    const size_t blockM = (size_t)blockIdx.x * 128;

    const int wm = wid >> 1, wn = wid & 1;
    float acc[2][8][4];
#pragma unroll
    for (int mi = 0; mi < 2; mi++)
#pragma unroll
        for (int ni = 0; ni < 8; ni++)
#pragma unroll
            for (int q = 0; q < 4; q++) acc[mi][ni][q] = 0.f;

    const int a_r = (lane & 7) + ((lane >> 3) & 1) * 8;
    const int a_c = (lane >> 4) * 8;
    const int b_r = (lane & 7) + (lane >> 4) * 8;
    const int b_c = ((lane >> 3) & 1) * 8;

    auto issue = [&](int c, int s) {
        int seg = c / KCH;
        int kc = (c - seg * KCH) * 64;
        const __half* Asrc;
        const __half* Bsrc;
        if (TERMS == 3) {
            Asrc = (seg == 2) ? Al : Ah;
            Bsrc = (seg == 1) ? Bl : Bh;
        } else {
            Asrc = (seg == 1) ? Al : Ah;
            Bsrc = Bh;
        }
        char* abase = dsm + s * 36864;
        char* bbase = abase + 18432;
#pragma unroll
        for (int u = tid; u < 1024; u += 256) {
            int r = u >> 3, j = u & 7;
            CP_ASYNC16(smem_u32(abase + r * 144 + j * 16),
                       Asrc + (blockM + r) * KS + kc + j * 8);
            CP_ASYNC16(smem_u32(bbase + r * 144 + j * 16),
                       Bsrc + (size_t)(ncol + r) * KS + kc + j * 8);
        }
        CP_COMMIT();
    };

    issue(0, 0);
    for (int c = 0; c < NCH; c++) {
        if (c + 1 < NCH) { issue(c + 1, (c + 1) & 1); CP_WAIT1(); }
        else             { CP_WAIT0(); }
        __syncthreads();
        char* abase = dsm + (c & 1) * 36864;
        char* bbase = abase + 18432;
#pragma unroll
        for (int ks = 0; ks < 4; ks++) {
            int k0 = ks * 16;
            uint32_t a[2][4];
#pragma unroll
            for (int mi = 0; mi < 2; mi++)
                ldsm_x4(a[mi], smem_u32(abase + (wm * 32 + mi * 16 + a_r) * 144 +
                                        (k0 + a_c) * 2));
            uint32_t b[4][4];
#pragma unroll
            for (int np = 0; np < 4; np++)
                ldsm_x4(b[np], smem_u32(bbase + (wn * 64 + np * 16 + b_r) * 144 +
                                        (k0 + b_c) * 2));
#pragma unroll
            for (int mi = 0; mi < 2; mi++)
#pragma unroll
                for (int ni = 0; ni < 8; ni++)
                    mma_f16(acc[mi][ni], a[mi],
                            b[ni >> 1][(ni & 1) * 2], b[ni >> 1][(ni & 1) * 2 + 1]);
        }
        __syncthreads();
    }

#pragma unroll
    for (int mi = 0; mi < 2; mi++) {
        int r0 = (int)blockM + wm * 32 + mi * 16 + (lane >> 2);
#pragma unroll
        for (int ni = 0; ni < 8; ni++) {
            int col = ncol + wn * 64 + ni * 8 + (lane & 3) * 2;
            if (r0 < NNODES)
                *(float2*)&Cd[(size_t)r0 * NPER + col] =
                    make_float2(acc[mi][ni][0], acc[mi][ni][1]);
            if (r0 + 8 < NNODES)
                *(float2*)&Cd[(size_t)(r0 + 8) * NPER + col] =
                    make_float2(acc[mi][ni][2], acc[mi][ni][3]);
        }
    }
}

// ---------------- layer 1 aggregation: half heads, 2 edges/warp-iter --------------
// warp per node; lane = g*16 + gl; group g handles edge pair member g.
// gl covers 8 channels of [half*128, half*128+128); head = subgroup of 8 lanes.
// logit reduce: xor 1,2,4; group combine at end via xor 16.
__global__ __launch_bounds__(256) void aggr1h(const float* __restrict__ att,
                                              const float* __restrict__ b1,
                                              int half) {
    int node = blockIdx.x * 8 + (threadIdx.x >> 5);
    if (node >= NNODES) return;
    int lane = threadIdx.x & 31;
    int g  = lane >> 4;
    int gl = lane & 15;
    int beg = g_row[node], end = g_row[node + 1];
    int ch = half * 128 + gl * 8;

    const float4* pr = (const float4*)(g_xr1 + (size_t)node * C1 + ch);
    float4 r0 = pr[0], r1 = pr[1];
    const float4* pa = (const float4*)(att + ch);
    float4 t0 = pa[0], t1 = pa[1];

    float acc[8];
#pragma unroll
    for (int q = 0; q < 8; q++) acc[q] = 0.f;
    float den = 0.f;

    int i = beg;
    while (i < end) {
        int cnt = min(32, end - i);
        int mysrc = __ldg(&g_srcs[i + min(lane, cnt - 1)]);
        for (int jb = 0; jb < cnt; jb += 2) {
            int idx = min(jb + g, cnt - 1);
            int src = __shfl_sync(0xffffffffu, mysrc, idx);
            bool valid = (jb + g) < cnt;
            const float4* pl = (const float4*)(g_xl1 + (size_t)src * C1 + ch);
            float4 a0 = __ldg(pl), a1 = __ldg(pl + 1);
            float s = lrelu(a0.x + r0.x) * t0.x + lrelu(a0.y + r0.y) * t0.y +
                      lrelu(a0.z + r0.z) * t0.z + lrelu(a0.w + r0.w) * t0.w +
                      lrelu(a1.x + r1.x) * t1.x + lrelu(a1.y + r1.y) * t1.y +
                      lrelu(a1.z + r1.z) * t1.z + lrelu(a1.w + r1.w) * t1.w;
            s += __shfl_xor_sync(0xffffffffu, s, 1);
            s += __shfl_xor_sync(0xffffffffu, s, 2);
            s += __shfl_xor_sync(0xffffffffu, s, 4);
            float ee = valid ? __expf(s) : 0.f;
            acc[0] = fmaf(ee, a0.x, acc[0]);
            acc[1] = fmaf(ee, a0.y, acc[1]);
            acc[2] = fmaf(ee, a0.z, acc[2]);
            acc[3] = fmaf(ee, a0.w, acc[3]);
            acc[4] = fmaf(ee, a1.x, acc[4]);
            acc[5] = fmaf(ee, a1.y, acc[5]);
            acc[6] = fmaf(ee, a1.z, acc[6]);
            acc[7] = fmaf(ee, a1.w, acc[7]);
            den += ee;
        }
        i += cnt;
    }
#pragma unroll
    for (int q = 0; q < 8; q++) acc[q] += __shfl_xor_sync(0xffffffffu, acc[q], 16);
    den += __shfl_xor_sync(0xffffffffu, den, 16);

    if (g == 0) {
        float inv = 1.f / (den + EPS_DEN);
        const float4* pb = (const float4*)(b1 + ch);
        float4 bb0 = pb[0], bb1 = pb[1];
        float o[8];
        o[0] = acc[0] * inv + bb0.x;  o[1] = acc[1] * inv + bb0.y;
        o[2] = acc[2] * inv + bb0.z;  o[3] = acc[3] * inv + bb0.w;
        o[4] = acc[4] * inv + bb1.x;  o[5] = acc[5] * inv + bb1.y;
        o[6] = acc[6] * inv + bb1.z;  o[7] = acc[7] * inv + bb1.w;
#pragma unroll
        for (int q = 0; q < 8; q++) o[q] = o[q] > 0.f ? o[q] : expm1f(o[q]);
        __half hv[8], lv[8];
#pragma unroll
        for (int q = 0; q < 8; q++) {
            hv[q] = __float2half_rn(o[q]);
            lv[q] = __float2half_rn(o[q] - __half2float(hv[q]));
        }
        *(uint4*)(g_ah + (size_t)node * 256 + ch) = *(const uint4*)hv;
        *(uint4*)(g_al + (size_t)node * 256 + ch) = *(const uint4*)lv;
    }
}

// ---------------- layer 2 aggregation: 2 edges/warp-iter ----------------
__global__ __launch_bounds__(256) void aggr2(const float* __restrict__ att,
                                             const float* __restrict__ b2,
                                             float* __restrict__ out) {
    int node = blockIdx.x * 8 + (threadIdx.x >> 5);
    if (node >= NNODES) return;
    int lane = threadIdx.x & 31;
    int g  = lane >> 4;
    int gl = lane & 15;
    int beg = g_row[node], end = g_row[node + 1];
    int ch = gl * 8;

    const float4* pr = (const float4*)(g_hr2 + (size_t)node * C2 + ch);
    float4 r0 = pr[0], r1 = pr[1];
    const float4* pa = (const float4*)(att + ch);
    float4 t0 = pa[0], t1 = pa[1];

    float acc[8];
#pragma unroll
    for (int q = 0; q < 8; q++) acc[q] = 0.f;
    float den = 0.f;

    int i = beg;
    while (i < end) {
        int cnt = min(32, end - i);
        int mysrc = __ldg(&g_srcs[i + min(lane, cnt - 1)]);
        for (int jb = 0; jb < cnt; jb += 2) {
            int idx = min(jb + g, cnt - 1);
            int src = __shfl_sync(0xffffffffu, mysrc, idx);
            bool valid = (jb + g) < cnt;
            const float4* pl = (const float4*)(g_hl2 + (size_t)src * C2 + ch);
            float4 a0 = __ldg(pl), a1 = __ldg(pl + 1);
            float s = lrelu(a0.x + r0.x) * t0.x + lrelu(a0.y + r0.y) * t0.y +
                      lrelu(a0.z + r0.z) * t0.z + lrelu(a0.w + r0.w) * t0.w +
                      lrelu(a1.x + r1.x) * t1.x + lrelu(a1.y + r1.y) * t1.y +
                      lrelu(a1.z + r1.z) * t1.z + lrelu(a1.w + r1.w) * t1.w;
            s += __shfl_xor_sync(0xffffffffu, s, 1);
            s += __shfl_xor_sync(0xffffffffu, s, 2);
            s += __shfl_xor_sync(0xffffffffu, s, 4);
            s += __shfl_xor_sync(0xffffffffu, s, 8);
            float ee = valid ? __expf(s) : 0.f;
            acc[0] = fmaf(ee, a0.x, acc[0]);
            acc[1] = fmaf(ee, a0.y, acc[1]);
            acc[2] = fmaf(ee, a0.z, acc[2]);
            acc[3] = fmaf(ee, a0.w, acc[3]);
            acc[4] = fmaf(ee, a1.x, acc[4]);
            acc[5] = fmaf(ee, a1.y, acc[5]);
            acc[6] = fmaf(ee, a1.z, acc[6]);
            acc[7] = fmaf(ee, a1.w, acc[7]);
            den += ee;
        }
        i += cnt;
    }
#pragma unroll
    for (int q = 0; q < 8; q++) acc[q] += __shfl_xor_sync(0xffffffffu, acc[q], 16);
    den += __shfl_xor_sync(0xffffffffu, den, 16);

    if (g == 0) {
        float inv = 1.f / (den + EPS_DEN);
        const float4* pb = (const float4*)(b2 + ch);
        float4 bb0 = pb[0], bb1 = pb[1];
        float4* po = (float4*)(out + (size_t)node * C2 + ch);
        po[0] = make_float4(acc[0] * inv + bb0.x, acc[1] * inv + bb0.y,
                            acc[2] * inv + bb0.z, acc[3] * inv + bb0.w);
        po[1] = make_float4(acc[4] * inv + bb1.x, acc[5] * inv + bb1.y,
                            acc[6] * inv + bb1.z, acc[7] * inv + bb1.w);
    }
}

// ---------------- launch ----------------
extern "C" void kernel_launch(void* const* d_in, const int* in_sizes, int n_in,
                              void* d_out, int out_size) {
    const float* x    = (const float*)d_in[0];
    const int*   ei   = (const int*)d_in[1];
    const float* Wl1  = (const float*)d_in[2];
    const float* Wr1  = (const float*)d_in[3];
    const float* att1 = (const float*)d_in[4];
    const float* b1   = (const float*)d_in[5];
    const float* Wl2  = (const float*)d_in[6];
    const float* Wr2  = (const float*)d_in[7];
    const float* att2 = (const float*)d_in[8];
    const float* b2   = (const float*)d_in[9];
    float* out = (float*)d_out;

    float *xl1, *xr1, *hl2, *hr2;
    __half *ah, *al, *bhL, *blL, *bhR, *blR, *bhL2, *blL2, *bhR2, *blR2;
    cudaGetSymbolAddress((void**)&xl1, g_xl1);
    cudaGetSymbolAddress((void**)&xr1, g_xr1);
    cudaGetSymbolAddress((void**)&hl2, g_hl2);
    cudaGetSymbolAddress((void**)&hr2, g_hr2);
    cudaGetSymbolAddress((void**)&ah,  g_ah);
    cudaGetSymbolAddress((void**)&al,  g_al);
    cudaGetSymbolAddress((void**)&bhL, g_bhL);
    cudaGetSymbolAddress((void**)&blL, g_blL);
    cudaGetSymbolAddress((void**)&bhR, g_bhR);
    cudaGetSymbolAddress((void**)&blR, g_blR);
    cudaGetSymbolAddress((void**)&bhL2, g_bhL2);
    cudaGetSymbolAddress((void**)&blL2, g_blL2);
    cudaGetSymbolAddress((void**)&bhR2, g_bhR2);
    cudaGetSymbolAddress((void**)&blR2, g_blR2);

    const int T = 256;
    const int DSMEM = 73728;
    cudaFuncSetAttribute((const void*)mgemm<128, 128, 256, 2>,
                         cudaFuncAttributeMaxDynamicSharedMemorySize, DSMEM);
    cudaFuncSetAttribute((const void*)mgemm<256, 256, 128, 2>,
                         cudaFuncAttributeMaxDynamicSharedMemorySize, DSMEM);

    // side stream for CSR build (fork-join; capture-legal).
    cudaStream_t s2;
    cudaStreamCreateWithFlags(&s2, cudaStreamNonBlocking);
    cudaEvent_t evF, evJ;
    cudaEventCreateWithFlags(&evF, cudaEventDisableTiming);
    cudaEventCreateWithFlags(&evJ, cudaEventDisableTiming);

    cudaEventRecord(evF, 0);
    cudaStreamWaitEvent(s2, evF, 0);
    k_zero<<<(NNODES + T - 1) / T, T, 0, s2>>>();
    k_count<<<(NEDGES + T - 1) / T, T, 0, s2>>>(ei);
    k_scan<<<1, 1024, 0, s2>>>();
    k_fill<<<(NEDGES + T - 1) / T, T, 0, s2>>>(ei);
    cudaEventRecord(evJ, s2);

    // main stream: merged weight split, input split, layer-1 dual GEMM (2-term)
    k_splitw4<<<(4 * 32768 + T - 1) / T, T>>>(Wl1, Wr1, Wl2, Wr2);
    k_split<<<(MPAD * 128 + T - 1) / T, T>>>(x, NNODES, 128);
    {
        dim3 grid(MPAD / 128, 4);
        mgemm<128, 128, 256, 2><<<grid, 256, DSMEM>>>(ah, al, bhL, blL, bhR, blR,
                                                      xl1, xr1);
    }

    // join: aggregation needs CSR + GEMM outputs
    cudaStreamWaitEvent(0, evJ, 0);

    int nblk = (NNODES + 7) / 8;
    aggr1h<<<nblk, 256>>>(att1, b1, 0);   // heads 0,1 (L2-resident pass)
    aggr1h<<<nblk, 256>>>(att1, b1, 1);   // heads 2,3

    // layer 2 dual GEMM (2-term fp16; consumes g_ah/g_al written by aggr1h)
    {
        dim3 grid(MPAD / 128, 2);
        mgemm<256, 256, 128, 2><<<grid, 256, DSMEM>>>(ah, al, bhL2, blL2, bhR2, blR2,
                                                      hl2, hr2);
    }
    aggr2<<<nblk, 256>>>(att2, b2, out);
}

// round 16
// speedup vs baseline: 1.5412x; 1.0284x over previous
#include <cuda_runtime.h>
#include <cuda_fp16.h>
#include <cstdint>

#define NNODES 50000
#define NEDGES 800000
#define MPAD   50048      // 391 * 128
#define C1 256            // heads*hid layer1
#define C2 128            // out channels layer2
#define NEG_SLOPE 0.2f
#define EPS_DEN 1e-16f

// ---------------- scratch (device globals; no allocations allowed) ----------------
__device__ __align__(16) __half g_xl1[NNODES * C1];
__device__ __align__(16) __half g_xr1[NNODES * C1];
__device__ __align__(16) __half g_hl2[NNODES * C2];
__device__ __align__(16) __half g_hr2[NNODES * C2];
__device__ int   g_row[NNODES + 1];
__device__ int   g_cnt[NNODES];
__device__ int   g_srcs[NEDGES];
// fp16 split buffers
__device__ __align__(16) __half g_ah[MPAD * 256];
__device__ __align__(16) __half g_al[MPAD * 256];
__device__ __align__(16) __half g_bhL[32768];
__device__ __align__(16) __half g_blL[32768];
__device__ __align__(16) __half g_bhR[32768];
__device__ __align__(16) __half g_blR[32768];
__device__ __align__(16) __half g_bhL2[32768];
__device__ __align__(16) __half g_blL2[32768];
__device__ __align__(16) __half g_bhR2[32768];
__device__ __align__(16) __half g_blR2[32768];

// ---------------- helpers ----------------
__device__ __forceinline__ float lrelu(float x) { return x > 0.f ? x : NEG_SLOPE * x; }

__device__ __forceinline__ uint32_t smem_u32(const void* p) {
    uint32_t a;
    asm("{ .reg .u64 t; cvta.to.shared.u64 t, %1; cvt.u32.u64 %0, t; }" : "=r"(a) : "l"(p));
    return a;
}

__device__ __forceinline__ void ldsm_x4(uint32_t* r, uint32_t addr) {
    asm volatile("ldmatrix.sync.aligned.m8n8.x4.shared.b16 {%0,%1,%2,%3}, [%4];"
                 : "=r"(r[0]), "=r"(r[1]), "=r"(r[2]), "=r"(r[3]) : "r"(addr));
}

__device__ __forceinline__ void mma_f16(float* c, const uint32_t* a,
                                        uint32_t b0, uint32_t b1) {
    asm volatile(
        "mma.sync.aligned.m16n8k16.row.col.f32.f16.f16.f32 "
        "{%0,%1,%2,%3}, {%4,%5,%6,%7}, {%8,%9}, {%0,%1,%2,%3};"
        : "+f"(c[0]), "+f"(c[1]), "+f"(c[2]), "+f"(c[3])
        : "r"(a[0]), "r"(a[1]), "r"(a[2]), "r"(a[3]), "r"(b0), "r"(b1));
}

// unpack 8 fp16 (uint4) -> 8 fp32
__device__ __forceinline__ void h8f(const uint4& v, float* f) {
    const __half2* h = (const __half2*)&v;
    float2 x;
    x = __half22float2(h[0]); f[0] = x.x; f[1] = x.y;
    x = __half22float2(h[1]); f[2] = x.x; f[3] = x.y;
    x = __half22float2(h[2]); f[4] = x.x; f[5] = x.y;
    x = __half22float2(h[3]); f[6] = x.x; f[7] = x.y;
}

#define CP_ASYNC16(dst, src) \
    asm volatile("cp.async.cg.shared.global [%0], [%1], 16;" :: "r"(dst), "l"(src))
#define CP_COMMIT() asm volatile("cp.async.commit_group;")
#define CP_WAIT1()  asm volatile("cp.async.wait_group 1;")
#define CP_WAIT0()  asm volatile("cp.async.wait_group 0;")

// ---------------- CSR build ----------------
__global__ void k_zero() {
    int i = blockIdx.x * blockDim.x + threadIdx.x;
    if (i < NNODES) g_cnt[i] = 0;
}
__global__ void k_count(const int* __restrict__ ei) {
    int e = blockIdx.x * blockDim.x + threadIdx.x;
    if (e < NEDGES) atomicAdd(&g_cnt[ei[NEDGES + e]], 1);
}
__global__ __launch_bounds__(1024) void k_scan() {
    __shared__ int s[1024];
    __shared__ int carry_s;
    int t = threadIdx.x;
    if (t == 0) carry_s = 0;
    __syncthreads();
    for (int base = 0; base < NNODES; base += 4096) {
        int idx = base + t * 4;
        int v0 = (idx + 0 < NNODES) ? g_cnt[idx + 0] : 0;
        int v1 = (idx + 1 < NNODES) ? g_cnt[idx + 1] : 0;
        int v2 = (idx + 2 < NNODES) ? g_cnt[idx + 2] : 0;
        int v3 = (idx + 3 < NNODES) ? g_cnt[idx + 3] : 0;
        int tot = v0 + v1 + v2 + v3;
        s[t] = tot;
        __syncthreads();
        for (int off = 1; off < 1024; off <<= 1) {
            int x = (t >= off) ? s[t - off] : 0;
            __syncthreads();
            s[t] += x;
            __syncthreads();
        }
        int excl = carry_s + s[t] - tot;
        if (idx + 0 < NNODES) { g_row[idx + 0] = excl;                g_cnt[idx + 0] = 0; }
        if (idx + 1 < NNODES) { g_row[idx + 1] = excl + v0;           g_cnt[idx + 1] = 0; }
        if (idx + 2 < NNODES) { g_row[idx + 2] = excl + v0 + v1;      g_cnt[idx + 2] = 0; }
        if (idx + 3 < NNODES) { g_row[idx + 3] = excl + v0 + v1 + v2; g_cnt[idx + 3] = 0; }
        __syncthreads();
        if (t == 1023) carry_s += s[1023];
        __syncthreads();
    }
    if (t == 0) g_row[NNODES] = NEDGES;
}
__global__ void k_fill(const int* __restrict__ ei) {
    int e = blockIdx.x * blockDim.x + threadIdx.x;
    if (e >= NEDGES) return;
    int dst = ei[NEDGES + e];
    int pos = g_row[dst] + atomicAdd(&g_cnt[dst], 1);
    g_srcs[pos] = ei[e];
}

// ---------------- fp16 hi/lo splits ----------------
__global__ void k_split(const float* __restrict__ A, int M, int K) {
    int i = blockIdx.x * blockDim.x + threadIdx.x;
    if (i >= MPAD * K) return;
    int m = i / K;
    float v = (m < M) ? A[i] : 0.f;
    __half h = __float2half_rn(v);
    g_ah[i] = h;
    g_al[i] = __float2half_rn(v - __half2float(h));
}

// all four weight splits in one launch. Segments of 32768 elements each.
__global__ void k_splitw4(const float* __restrict__ Wl1, const float* __restrict__ Wr1,
                          const float* __restrict__ Wl2, const float* __restrict__ Wr2) {
    int i = blockIdx.x * blockDim.x + threadIdx.x;
    if (i >= 4 * 32768) return;
    int seg = i >> 15;
    int j = i & 32767;
    const float* W;
    __half *bh, *bl;
    int K, Nn;
    if (seg == 0)      { W = Wl1; bh = g_bhL;  bl = g_blL;  K = 128; Nn = 256; }
    else if (seg == 1) { W = Wr1; bh = g_bhR;  bl = g_blR;  K = 128; Nn = 256; }
    else if (seg == 2) { W = Wl2; bh = g_bhL2; bl = g_blL2; K = 256; Nn = 128; }
    else               { W = Wr2; bh = g_bhR2; bl = g_blR2; K = 256; Nn = 128; }
    int k = j / Nn, n = j - k * Nn;
    float v = W[j];
    __half h = __float2half_rn(v);
    bh[n * K + k] = h;
    bl[n * K + k] = __float2half_rn(v - __half2float(h));
}

// ---------------- warp-MMA fp16 GEMM, cp.async double-buffered --------------------
// KS = row stride of A/B (elems); KT = K width. Output: fp16 (half2 stores).
// TERMS=2: Ah*Bh + Al*Bh (B single fp16)
template <int KS, int KT, int NPER, int TERMS>
__global__ __launch_bounds__(256) void mgemm(
    const __half* __restrict__ Ah, const __half* __restrict__ Al,
    const __half* __restrict__ Bh0, const __half* __restrict__ Bl0,
    const __half* __restrict__ Bh1, const __half* __restrict__ Bl1,
    __half* __restrict__ Cd0, __half* __restrict__ Cd1) {
    constexpr int KCH = KT / 64;
    constexpr int NCH = TERMS * KCH;
    constexpr int NB  = NPER / 128;
    extern __shared__ char dsm[];

    const int tid = threadIdx.x, wid = tid >> 5, lane = tid & 31;
    const int mat  = blockIdx.y / NB;
    const int ncol = (blockIdx.y % NB) * 128;
    const __half* Bh = mat ? Bh1 : Bh0;
    const __half* Bl = mat ? Bl1 : Bl0;
    __half* Cd = mat ? Cd1 : Cd0;
    const size_t blockM = (size_t)blockIdx.x * 128;

    const int wm = wid >> 1, wn = wid & 1;
    float acc[2][8][4];
#pragma unroll
    for (int mi = 0; mi < 2; mi++)
#pragma unroll
        for (int ni = 0; ni < 8; ni++)
#pragma unroll
            for (int q = 0; q < 4; q++) acc[mi][ni][q] = 0.f;

    const int a_r = (lane & 7) + ((lane >> 3) & 1) * 8;
    const int a_c = (lane >> 4) * 8;
    const int b_r = (lane & 7) + (lane >> 4) * 8;
    const int b_c = ((lane >> 3) & 1) * 8;

    auto issue = [&](int c, int s) {
        int seg = c / KCH;
        int kc = (c - seg * KCH) * 64;
        const __half* Asrc;
        const __half* Bsrc;
        if (TERMS == 3) {
            Asrc = (seg == 2) ? Al : Ah;
            Bsrc = (seg == 1) ? Bl : Bh;
        } else {
            Asrc = (seg == 1) ? Al : Ah;
            Bsrc = Bh;
        }
        char* abase = dsm + s * 36864;
        char* bbase = abase + 18432;
#pragma unroll
        for (int u = tid; u < 1024; u += 256) {
            int r = u >> 3, j = u & 7;
            CP_ASYNC16(smem_u32(abase + r * 144 + j * 16),
                       Asrc + (blockM + r) * KS + kc + j * 8);
            CP_ASYNC16(smem_u32(bbase + r * 144 + j * 16),
                       Bsrc + (size_t)(ncol + r) * KS + kc + j * 8);
        }
        CP_COMMIT();
    };

    issue(0, 0);
    for (int c = 0; c < NCH; c++) {
        if (c + 1 < NCH) { issue(c + 1, (c + 1) & 1); CP_WAIT1(); }
        else             { CP_WAIT0(); }
        __syncthreads();
        char* abase = dsm + (c & 1) * 36864;
        char* bbase = abase + 18432;
#pragma unroll
        for (int ks = 0; ks < 4; ks++) {
            int k0 = ks * 16;
            uint32_t a[2][4];
#pragma unroll
            for (int mi = 0; mi < 2; mi++)
                ldsm_x4(a[mi], smem_u32(abase + (wm * 32 + mi * 16 + a_r) * 144 +
                                        (k0 + a_c) * 2));
            uint32_t b[4][4];
#pragma unroll
            for (int np = 0; np < 4; np++)
                ldsm_x4(b[np], smem_u32(bbase + (wn * 64 + np * 16 + b_r) * 144 +
                                        (k0 + b_c) * 2));
#pragma unroll
            for (int mi = 0; mi < 2; mi++)
#pragma unroll
                for (int ni = 0; ni < 8; ni++)
                    mma_f16(acc[mi][ni], a[mi],
                            b[ni >> 1][(ni & 1) * 2], b[ni >> 1][(ni & 1) * 2 + 1]);
        }
        __syncthreads();
    }

#pragma unroll
    for (int mi = 0; mi < 2; mi++) {
        int r0 = (int)blockM + wm * 32 + mi * 16 + (lane >> 2);
#pragma unroll
        for (int ni = 0; ni < 8; ni++) {
            int col = ncol + wn * 64 + ni * 8 + (lane & 3) * 2;
            if (r0 < NNODES)
                *(__half2*)&Cd[(size_t)r0 * NPER + col] =
                    __floats2half2_rn(acc[mi][ni][0], acc[mi][ni][1]);
            if (r0 + 8 < NNODES)
                *(__half2*)&Cd[(size_t)(r0 + 8) * NPER + col] =
                    __floats2half2_rn(acc[mi][ni][2], acc[mi][ni][3]);
        }
    }
}

// ---------------- layer 1 aggregation: half heads, 2 edges/warp-iter, fp16 gathers -
// warp per node; lane = g*16 + gl; group g handles edge pair member g.
// gl covers 8 channels of [half*128, half*128+128); head = subgroup of 8 lanes.
// logit reduce: xor 1,2,4; group combine at end via xor 16.
__global__ __launch_bounds__(256) void aggr1h(const float* __restrict__ att,
                                              const float* __restrict__ b1,
                                              int half) {
    int node = blockIdx.x * 8 + (threadIdx.x >> 5);
    if (node >= NNODES) return;
    int lane = threadIdx.x & 31;
    int g  = lane >> 4;
    int gl = lane & 15;
    int beg = g_row[node], end = g_row[node + 1];
    int ch = half * 128 + gl * 8;

    float rr[8];
    { uint4 rv = *(const uint4*)(g_xr1 + (size_t)node * C1 + ch); h8f(rv, rr); }
    const float4* pa = (const float4*)(att + ch);
    float4 t0 = pa[0], t1 = pa[1];
    float tt[8] = {t0.x, t0.y, t0.z, t0.w, t1.x, t1.y, t1.z, t1.w};

    float acc[8];
#pragma unroll
    for (int q = 0; q < 8; q++) acc[q] = 0.f;
    float den = 0.f;

    int i = beg;
    while (i < end) {
        int cnt = min(32, end - i);
        int mysrc = __ldg(&g_srcs[i + min(lane, cnt - 1)]);
        for (int jb = 0; jb < cnt; jb += 2) {
            int idx = min(jb + g, cnt - 1);
            int src = __shfl_sync(0xffffffffu, mysrc, idx);
            bool valid = (jb + g) < cnt;
            uint4 av = __ldg((const uint4*)(g_xl1 + (size_t)src * C1 + ch));
            float aa[8];
            h8f(av, aa);
            float s = 0.f;
#pragma unroll
            for (int q = 0; q < 8; q++) s = fmaf(lrelu(aa[q] + rr[q]), tt[q], s);
            s += __shfl_xor_sync(0xffffffffu, s, 1);
            s += __shfl_xor_sync(0xffffffffu, s, 2);
            s += __shfl_xor_sync(0xffffffffu, s, 4);
            float ee = valid ? __expf(s) : 0.f;
#pragma unroll
            for (int q = 0; q < 8; q++) acc[q] = fmaf(ee, aa[q], acc[q]);
            den += ee;
        }
        i += cnt;
    }
#pragma unroll
    for (int q = 0; q < 8; q++) acc[q] += __shfl_xor_sync(0xffffffffu, acc[q], 16);
    den += __shfl_xor_sync(0xffffffffu, den, 16);

    if (g == 0) {
        float inv = 1.f / (den + EPS_DEN);
        const float4* pb = (const float4*)(b1 + ch);
        float4 bb0 = pb[0], bb1 = pb[1];
        float bb[8] = {bb0.x, bb0.y, bb0.z, bb0.w, bb1.x, bb1.y, bb1.z, bb1.w};
        float o[8];
#pragma unroll
        for (int q = 0; q < 8; q++) {
            float v = acc[q] * inv + bb[q];
            o[q] = v > 0.f ? v : expm1f(v);
        }
        __half hv[8], lv[8];
#pragma unroll
        for (int q = 0; q < 8; q++) {
            hv[q] = __float2half_rn(o[q]);
            lv[q] = __float2half_rn(o[q] - __half2float(hv[q]));
        }
        *(uint4*)(g_ah + (size_t)node * 256 + ch) = *(const uint4*)hv;
        *(uint4*)(g_al + (size_t)node * 256 + ch) = *(const uint4*)lv;
    }
}

// ---------------- layer 2 aggregation: 2 edges/warp-iter, fp16 gathers -------------
__global__ __launch_bounds__(256) void aggr2(const float* __restrict__ att,
                                             const float* __restrict__ b2,
                                             float* __restrict__ out) {
    int node = blockIdx.x * 8 + (threadIdx.x >> 5);
    if (node >= NNODES) return;
    int lane = threadIdx.x & 31;
    int g  = lane >> 4;
    int gl = lane & 15;
    int beg = g_row[node], end = g_row[node + 1];
    int ch = gl * 8;

    float rr[8];
    { uint4 rv = *(const uint4*)(g_hr2 + (size_t)node * C2 + ch); h8f(rv, rr); }
    const float4* pa = (const float4*)(att + ch);
    float4 t0 = pa[0], t1 = pa[1];
    float tt[8] = {t0.x, t0.y, t0.z, t0.w, t1.x, t1.y, t1.z, t1.w};

    float acc[8];
#pragma unroll
    for (int q = 0; q < 8; q++) acc[q] = 0.f;
    float den = 0.f;

    int i = beg;
    while (i < end) {
        int cnt = min(32, end - i);
        int mysrc = __ldg(&g_srcs[i + min(lane, cnt - 1)]);
        for (int jb = 0; jb < cnt; jb += 2) {
            int idx = min(jb + g, cnt - 1);
            int src = __shfl_sync(0xffffffffu, mysrc, idx);
            bool valid = (jb + g) < cnt;
            uint4 av = __ldg((const uint4*)(g_hl2 + (size_t)src * C2 + ch));
            float aa[8];
            h8f(av, aa);
            float s = 0.f;
#pragma unroll
            for (int q = 0; q < 8; q++) s = fmaf(lrelu(aa[q] + rr[q]), tt[q], s);
            s += __shfl_xor_sync(0xffffffffu, s, 1);
            s += __shfl_xor_sync(0xffffffffu, s, 2);
            s += __shfl_xor_sync(0xffffffffu, s, 4);
            s += __shfl_xor_sync(0xffffffffu, s, 8);
            float ee = valid ? __expf(s) : 0.f;
#pragma unroll
            for (int q = 0; q < 8; q++) acc[q] = fmaf(ee, aa[q], acc[q]);
            den += ee;
        }
        i += cnt;
    }
#pragma unroll
    for (int q = 0; q < 8; q++) acc[q] += __shfl_xor_sync(0xffffffffu, acc[q], 16);
    den += __shfl_xor_sync(0xffffffffu, den, 16);

    if (g == 0) {
        float inv = 1.f / (den + EPS_DEN);
        const float4* pb = (const float4*)(b2 + ch);
        float4 bb0 = pb[0], bb1 = pb[1];
        float4* po = (float4*)(out + (size_t)node * C2 + ch);
        po[0] = make_float4(acc[0] * inv + bb0.x, acc[1] * inv + bb0.y,
                            acc[2] * inv + bb0.z, acc[3] * inv + bb0.w);
        po[1] = make_float4(acc[4] * inv + bb1.x, acc[5] * inv + bb1.y,
                            acc[6] * inv + bb1.z, acc[7] * inv + bb1.w);
    }
}

// ---------------- launch ----------------
extern "C" void kernel_launch(void* const* d_in, const int* in_sizes, int n_in,
                              void* d_out, int out_size) {
    const float* x    = (const float*)d_in[0];
    const int*   ei   = (const int*)d_in[1];
    const float* Wl1  = (const float*)d_in[2];
    const float* Wr1  = (const float*)d_in[3];
    const float* att1 = (const float*)d_in[4];
    const float* b1   = (const float*)d_in[5];
    const float* Wl2  = (const float*)d_in[6];
    const float* Wr2  = (const float*)d_in[7];
    const float* att2 = (const float*)d_in[8];
    const float* b2   = (const float*)d_in[9];
    float* out = (float*)d_out;

    __half *xl1, *xr1, *hl2, *hr2;
    __half *ah, *al, *bhL, *blL, *bhR, *blR, *bhL2, *blL2, *bhR2, *blR2;
    cudaGetSymbolAddress((void**)&xl1, g_xl1);
    cudaGetSymbolAddress((void**)&xr1, g_xr1);
    cudaGetSymbolAddress((void**)&hl2, g_hl2);
    cudaGetSymbolAddress((void**)&hr2, g_hr2);
    cudaGetSymbolAddress((void**)&ah,  g_ah);
    cudaGetSymbolAddress((void**)&al,  g_al);
    cudaGetSymbolAddress((void**)&bhL, g_bhL);
    cudaGetSymbolAddress((void**)&blL, g_blL);
    cudaGetSymbolAddress((void**)&bhR, g_bhR);
    cudaGetSymbolAddress((void**)&blR, g_blR);
    cudaGetSymbolAddress((void**)&bhL2, g_bhL2);
    cudaGetSymbolAddress((void**)&blL2, g_blL2);
    cudaGetSymbolAddress((void**)&bhR2, g_bhR2);
    cudaGetSymbolAddress((void**)&blR2, g_blR2);

    const int T = 256;
    const int DSMEM = 73728;
    cudaFuncSetAttribute((const void*)mgemm<128, 128, 256, 2>,
                         cudaFuncAttributeMaxDynamicSharedMemorySize, DSMEM);
    cudaFuncSetAttribute((const void*)mgemm<256, 256, 128, 2>,
                         cudaFuncAttributeMaxDynamicSharedMemorySize, DSMEM);

    // side stream for CSR build (fork-join; capture-legal).
    cudaStream_t s2;
    cudaStreamCreateWithFlags(&s2, cudaStreamNonBlocking);
    cudaEvent_t evF, evJ;
    cudaEventCreateWithFlags(&evF, cudaEventDisableTiming);
    cudaEventCreateWithFlags(&evJ, cudaEventDisableTiming);

    cudaEventRecord(evF, 0);
    cudaStreamWaitEvent(s2, evF, 0);
    k_zero<<<(NNODES + T - 1) / T, T, 0, s2>>>();
    k_count<<<(NEDGES + T - 1) / T, T, 0, s2>>>(ei);
    k_scan<<<1, 1024, 0, s2>>>();
    k_fill<<<(NEDGES + T - 1) / T, T, 0, s2>>>(ei);
    cudaEventRecord(evJ, s2);

    // main stream: merged weight split, input split, layer-1 dual GEMM (2-term)
    k_splitw4<<<(4 * 32768 + T - 1) / T, T>>>(Wl1, Wr1, Wl2, Wr2);
    k_split<<<(MPAD * 128 + T - 1) / T, T>>>(x, NNODES, 128);
    {
        dim3 grid(MPAD / 128, 4);
        mgemm<128, 128, 256, 2><<<grid, 256, DSMEM>>>(ah, al, bhL, blL, bhR, blR,
                                                      xl1, xr1);
    }

    // join: aggregation needs CSR + GEMM outputs
    cudaStreamWaitEvent(0, evJ, 0);

    int nblk = (NNODES + 7) / 8;
    aggr1h<<<nblk, 256>>>(att1, b1, 0);   // heads 0,1 (L2-resident pass)
    aggr1h<<<nblk, 256>>>(att1, b1, 1);   // heads 2,3

    // layer 2 dual GEMM (2-term fp16; consumes g_ah/g_al written by aggr1h)
    {
        dim3 grid(MPAD / 128, 2);
        mgemm<256, 256, 128, 2><<<grid, 256, DSMEM>>>(ah, al, bhL2, blL2, bhR2, blR2,
                                                      hl2, hr2);
    }
    aggr2<<<nblk, 256>>>(att2, b2, out);
}